// round 2
// baseline (speedup 1.0000x reference)
#include <cuda_runtime.h>
#include <cstdint>

#define B_  64
#define T_  320
#define E_  1024
#define H_  16
#define HS_ 64
#define P_  4096
#define M_  (B_ * T_)          // 20480 tokens
#define EPS 1e-5f
#define SCALE 0.03125f          // E^-0.5 = 1/32

typedef unsigned long long ull;

// ---------------- packed f32x2 helpers (sm_100+) ----------------
__device__ __forceinline__ ull pack2(float x) {
    ull r;
    asm("mov.b64 %0, {%1, %1};" : "=l"(r) : "f"(x));
    return r;
}
__device__ __forceinline__ void ffma2(ull& d, ull a, ull b) {
    asm("fma.rn.f32x2 %0, %1, %2, %0;" : "+l"(d) : "l"(a), "l"(b));
}
__device__ __forceinline__ ull mul2(ull a, ull b) {
    ull r;
    asm("mul.rn.f32x2 %0, %1, %2;" : "=l"(r) : "l"(a), "l"(b));
    return r;
}
__device__ __forceinline__ float2 unpack2(ull v) {
    union { ull u; float2 f; } c;
    c.u = v;
    return c.f;
}

// ---------------- scratch (device globals; no allocation allowed) ----------------
__device__ float g_h[(size_t)M_ * E_];
__device__ float g_w3[(size_t)E_ * 3 * E_];
__device__ float g_qkv[(size_t)M_ * 3 * E_];
__device__ float g_attn[(size_t)M_ * E_];
__device__ float g_x2[(size_t)M_ * E_];
__device__ float g_u[(size_t)M_ * P_];

// ---------------- pack Wq/Wk/Wv -> [k][which*1024 + h*64 + d] ----------------
__global__ void pack_w_kernel(const float* __restrict__ Wq,
                              const float* __restrict__ Wk,
                              const float* __restrict__ Wv,
                              float* __restrict__ W3) {
    int idx = blockIdx.x * 256 + threadIdx.x;
    int k = idx / 3072;
    int n = idx % 3072;
    int which = n >> 10;
    int rem = n & 1023;
    int hh = rem >> 6;
    int d = rem & 63;
    const float* W = (which == 0) ? Wq : (which == 1) ? Wk : Wv;
    W3[idx] = W[(size_t)hh * E_ * HS_ + (size_t)k * HS_ + d];
}

// ---------------- layernorm ----------------
__device__ __forceinline__ float blockSum256(float v, float* sh) {
    __syncthreads();
    #pragma unroll
    for (int o = 16; o > 0; o >>= 1) v += __shfl_xor_sync(0xffffffffu, v, o);
    if ((threadIdx.x & 31) == 0) sh[threadIdx.x >> 5] = v;
    __syncthreads();
    if (threadIdx.x < 32) {
        float t = (threadIdx.x < 8) ? sh[threadIdx.x] : 0.0f;
        #pragma unroll
        for (int o = 4; o > 0; o >>= 1) t += __shfl_xor_sync(0xffffffffu, t, o);
        if (threadIdx.x == 0) sh[0] = t;
    }
    __syncthreads();
    return sh[0];
}

__global__ void ln_kernel(const float* __restrict__ x, const float* __restrict__ w,
                          const float* __restrict__ bb, float* __restrict__ out) {
    __shared__ float sh[8];
    size_t row = blockIdx.x;
    int tid = threadIdx.x;
    const float4 v = ((const float4*)(x + row * E_))[tid];
    float s = v.x + v.y + v.z + v.w;
    s = blockSum256(s, sh);
    float mu = s * (1.0f / E_);
    float dx = v.x - mu, dy = v.y - mu, dz = v.z - mu, dw = v.w - mu;
    float ss = dx * dx + dy * dy + dz * dz + dw * dw;
    ss = blockSum256(ss, sh);
    float inv = rsqrtf(ss * (1.0f / E_) + EPS);
    float4 w4 = ((const float4*)w)[tid];
    float4 b4 = ((const float4*)bb)[tid];
    float4 r;
    r.x = dx * inv * w4.x + b4.x;
    r.y = dy * inv * w4.y + b4.y;
    r.z = dz * inv * w4.z + b4.z;
    r.w = dw * inv * w4.w + b4.w;
    ((float4*)(out + row * E_))[tid] = r;
}

// ---------------- 128x128x8 SGEMM: FFMA2 core + double-buffered smem ----------------
template <bool BIAS, bool RESID, bool RELU>
__global__ __launch_bounds__(256, 2) void gemm128_kernel(
    const float* __restrict__ A, const float* __restrict__ Bm,
    const float* __restrict__ bias, const float* __restrict__ Rm,
    float* __restrict__ C, int Ndim, int K) {
    __shared__ float As[2][8][128];
    __shared__ float Bs[2][8][132];

    int tid = threadIdx.x;
    int bx = blockIdx.x, by = blockIdx.y;
    int tx = tid & 15, ty = tid >> 4;

    const float* Ap = A + (size_t)by * 128 * K;
    const float* Bp = Bm + (size_t)bx * 128;

    int a_row = tid >> 1, a_col = (tid & 1) * 4;
    int b_row = tid >> 5, b_col = (tid & 31) * 4;

    float4 aF = *(const float4*)(Ap + (size_t)a_row * K + a_col);
    float4 bF = *(const float4*)(Bp + (size_t)b_row * Ndim + b_col);

    ull acc[8][4];
    #pragma unroll
    for (int i = 0; i < 8; i++)
        #pragma unroll
        for (int j = 0; j < 4; j++) acc[i][j] = 0ull;

    // store tile 0
    As[0][a_col + 0][a_row] = aF.x;
    As[0][a_col + 1][a_row] = aF.y;
    As[0][a_col + 2][a_row] = aF.z;
    As[0][a_col + 3][a_row] = aF.w;
    *(float4*)&Bs[0][b_row][b_col] = bF;
    __syncthreads();

    int nk = K >> 3;
    for (int kt = 0; kt < nk; kt++) {
        int cur = kt & 1;
        if (kt + 1 < nk) {
            aF = *(const float4*)(Ap + (size_t)a_row * K + (kt + 1) * 8 + a_col);
            bF = *(const float4*)(Bp + (size_t)((kt + 1) * 8 + b_row) * Ndim + b_col);
        }
        #pragma unroll
        for (int kk = 0; kk < 8; kk++) {
            float ar[8];
            *(float4*)&ar[0] = *(float4*)&As[cur][kk][ty * 8];
            *(float4*)&ar[4] = *(float4*)&As[cur][kk][ty * 8 + 4];
            ull bp[4];
            #pragma unroll
            for (int j = 0; j < 4; j++)
                bp[j] = *(const ull*)&Bs[cur][kk][tx * 8 + j * 2];
            #pragma unroll
            for (int i = 0; i < 8; i++) {
                ull ap = pack2(ar[i]);
                #pragma unroll
                for (int j = 0; j < 4; j++) ffma2(acc[i][j], ap, bp[j]);
            }
        }
        if (kt + 1 < nk) {
            int nxt = cur ^ 1;
            As[nxt][a_col + 0][a_row] = aF.x;
            As[nxt][a_col + 1][a_row] = aF.y;
            As[nxt][a_col + 2][a_row] = aF.z;
            As[nxt][a_col + 3][a_row] = aF.w;
            *(float4*)&Bs[nxt][b_row][b_col] = bF;
            __syncthreads();
        }
    }

    int m0 = by * 128 + ty * 8;
    int n0 = bx * 128 + tx * 8;
    #pragma unroll
    for (int i = 0; i < 8; i++) {
        size_t rowoff = (size_t)(m0 + i) * Ndim + n0;
        #pragma unroll
        for (int j4 = 0; j4 < 2; j4++) {
            float2 lo = unpack2(acc[i][j4 * 2 + 0]);
            float2 hi = unpack2(acc[i][j4 * 2 + 1]);
            float4 v;
            v.x = lo.x; v.y = lo.y; v.z = hi.x; v.w = hi.y;
            if (BIAS) {
                float4 bb = *(const float4*)(bias + n0 + j4 * 4);
                v.x += bb.x; v.y += bb.y; v.z += bb.z; v.w += bb.w;
            }
            if (RESID) {
                float4 rr = *(const float4*)(Rm + rowoff + j4 * 4);
                v.x += rr.x; v.y += rr.y; v.z += rr.z; v.w += rr.w;
            }
            if (RELU) {
                v.x = fmaxf(v.x, 0.0f); v.y = fmaxf(v.y, 0.0f);
                v.z = fmaxf(v.z, 0.0f); v.w = fmaxf(v.w, 0.0f);
            }
            *(float4*)(C + rowoff + j4 * 4) = v;
        }
    }
}

// ---------------- flash attention with FFMA2 cores ----------------
#define APAD 68
__global__ __launch_bounds__(256) void attn_kernel(const float* __restrict__ qkv,
                                                   float* __restrict__ out) {
    extern __shared__ float sm[];
    float* Qt  = sm;                 // Qt[d][r]
    float* Kst = sm + 64 * APAD;     // Kst[d][kc]
    float* Vs  = sm + 2 * 64 * APAD; // Vs[kc][d]
    float* St  = sm + 3 * 64 * APAD; // St[kc][qr]

    int qt = blockIdx.x, h = blockIdx.y, b = blockIdx.z;
    int tid = threadIdx.x, tx = tid & 15, ty = tid >> 4;
    int t0 = qt * 64;
    size_t base = (size_t)b * T_ * 3072;

    #pragma unroll
    for (int l = 0; l < 4; l++) {
        int idx = l * 256 + tid;
        int r = idx >> 4;
        int d4 = (idx & 15) * 4;
        float4 v = *(const float4*)(qkv + base + (size_t)(t0 + r) * 3072 + h * 64 + d4);
        Qt[(d4 + 0) * APAD + r] = v.x;
        Qt[(d4 + 1) * APAD + r] = v.y;
        Qt[(d4 + 2) * APAD + r] = v.z;
        Qt[(d4 + 3) * APAD + r] = v.w;
    }

    ull o2[4][2];
    float m[4], l_[4];
    #pragma unroll
    for (int i = 0; i < 4; i++) {
        m[i] = -1e30f; l_[i] = 0.0f;
        o2[i][0] = 0ull; o2[i][1] = 0ull;
    }

    for (int ktile = 0; ktile <= qt; ++ktile) {
        __syncthreads();
        int k0 = ktile * 64;
        #pragma unroll
        for (int l = 0; l < 4; l++) {
            int idx = l * 256 + tid;
            int r = idx >> 4;
            int d4 = (idx & 15) * 4;
            float4 kv = *(const float4*)(qkv + base + (size_t)(k0 + r) * 3072 + 1024 + h * 64 + d4);
            Kst[(d4 + 0) * APAD + r] = kv.x;
            Kst[(d4 + 1) * APAD + r] = kv.y;
            Kst[(d4 + 2) * APAD + r] = kv.z;
            Kst[(d4 + 3) * APAD + r] = kv.w;
            float4 vv = *(const float4*)(qkv + base + (size_t)(k0 + r) * 3072 + 2048 + h * 64 + d4);
            *(float4*)&Vs[r * APAD + d4] = vv;
        }
        __syncthreads();

        ull s2[4][2];
        #pragma unroll
        for (int i = 0; i < 4; i++) { s2[i][0] = 0ull; s2[i][1] = 0ull; }

        for (int d = 0; d < 64; d++) {
            float4 a = *(float4*)&Qt[d * APAD + ty * 4];
            ull c0 = *(ull*)&Kst[d * APAD + tx * 4];
            ull c1 = *(ull*)&Kst[d * APAD + tx * 4 + 2];
            float av[4] = {a.x, a.y, a.z, a.w};
            #pragma unroll
            for (int i = 0; i < 4; i++) {
                ull ap = pack2(av[i]);
                ffma2(s2[i][0], ap, c0);
                ffma2(s2[i][1], ap, c1);
            }
        }

        float s[4][4];
        #pragma unroll
        for (int i = 0; i < 4; i++) {
            float2 lo = unpack2(s2[i][0]);
            float2 hi = unpack2(s2[i][1]);
            s[i][0] = lo.x * SCALE; s[i][1] = lo.y * SCALE;
            s[i][2] = hi.x * SCALE; s[i][3] = hi.y * SCALE;
        }

        if (ktile == qt) {
            #pragma unroll
            for (int i = 0; i < 4; i++)
                #pragma unroll
                for (int j = 0; j < 4; j++)
                    if (k0 + tx * 4 + j > t0 + ty * 4 + i) s[i][j] = -1e30f;
        }

        #pragma unroll
        for (int i = 0; i < 4; i++) {
            float mx = fmaxf(fmaxf(s[i][0], s[i][1]), fmaxf(s[i][2], s[i][3]));
            #pragma unroll
            for (int off = 8; off > 0; off >>= 1)
                mx = fmaxf(mx, __shfl_xor_sync(0xffffffffu, mx, off, 16));
            float mn = fmaxf(m[i], mx);
            float al = __expf(m[i] - mn);
            float rs = 0.0f;
            #pragma unroll
            for (int j = 0; j < 4; j++) {
                float p = __expf(s[i][j] - mn);
                s[i][j] = p;
                rs += p;
            }
            #pragma unroll
            for (int off = 8; off > 0; off >>= 1)
                rs += __shfl_xor_sync(0xffffffffu, rs, off, 16);
            l_[i] = l_[i] * al + rs;
            m[i] = mn;
            ull al2 = pack2(al);
            o2[i][0] = mul2(o2[i][0], al2);
            o2[i][1] = mul2(o2[i][1], al2);
            #pragma unroll
            for (int j = 0; j < 4; j++)
                St[(tx * 4 + j) * APAD + ty * 4 + i] = s[i][j];
        }
        __syncthreads();

        for (int kc = 0; kc < 64; kc++) {
            float4 a = *(float4*)&St[kc * APAD + ty * 4];
            ull v0 = *(ull*)&Vs[kc * APAD + tx * 4];
            ull v1 = *(ull*)&Vs[kc * APAD + tx * 4 + 2];
            float av[4] = {a.x, a.y, a.z, a.w};
            #pragma unroll
            for (int i = 0; i < 4; i++) {
                ull ap = pack2(av[i]);
                ffma2(o2[i][0], ap, v0);
                ffma2(o2[i][1], ap, v1);
            }
        }
    }

    #pragma unroll
    for (int i = 0; i < 4; i++) {
        float inv = 1.0f / l_[i];
        float2 lo = unpack2(o2[i][0]);
        float2 hi = unpack2(o2[i][1]);
        float4 v;
        v.x = lo.x * inv; v.y = lo.y * inv;
        v.z = hi.x * inv; v.w = hi.y * inv;
        *(float4*)(out + ((size_t)b * T_ + t0 + ty * 4 + i) * E_ + h * 64 + tx * 4) = v;
    }
}

// ---------------- launch ----------------
extern "C" void kernel_launch(void* const* d_in, const int* in_sizes, int n_in,
                              void* d_out, int out_size) {
    const float* x     = (const float*)d_in[0];
    const float* Wq    = (const float*)d_in[1];
    const float* Wk    = (const float*)d_in[2];
    const float* Wv    = (const float*)d_in[3];
    const float* Wo    = (const float*)d_in[4];
    const float* bo    = (const float*)d_in[5];
    const float* W1    = (const float*)d_in[6];
    const float* b1    = (const float*)d_in[7];
    const float* W2    = (const float*)d_in[8];
    const float* b2    = (const float*)d_in[9];
    const float* ln1w  = (const float*)d_in[10];
    const float* ln1b  = (const float*)d_in[11];
    const float* ln2w  = (const float*)d_in[12];
    const float* ln2b  = (const float*)d_in[13];
    float* out = (float*)d_out;

    float *h, *w3, *qkv, *attn, *x2, *u;
    cudaGetSymbolAddress((void**)&h, g_h);
    cudaGetSymbolAddress((void**)&w3, g_w3);
    cudaGetSymbolAddress((void**)&qkv, g_qkv);
    cudaGetSymbolAddress((void**)&attn, g_attn);
    cudaGetSymbolAddress((void**)&x2, g_x2);
    cudaGetSymbolAddress((void**)&u, g_u);

    cudaFuncSetAttribute(attn_kernel, cudaFuncAttributeMaxDynamicSharedMemorySize,
                         4 * 64 * APAD * 4);

    pack_w_kernel<<<(3 * E_ * E_) / 256, 256>>>(Wq, Wk, Wv, w3);
    ln_kernel<<<M_, 256>>>(x, ln1w, ln1b, h);
    gemm128_kernel<false, false, false><<<dim3(3072 / 128, M_ / 128), 256>>>(
        h, w3, nullptr, nullptr, qkv, 3072, E_);
    attn_kernel<<<dim3(T_ / 64, H_, B_), 256, 4 * 64 * APAD * 4>>>(qkv, attn);
    gemm128_kernel<true, true, false><<<dim3(E_ / 128, M_ / 128), 256>>>(
        attn, Wo, bo, x, x2, E_, E_);
    ln_kernel<<<M_, 256>>>(x2, ln2w, ln2b, h);
    gemm128_kernel<true, false, true><<<dim3(P_ / 128, M_ / 128), 256>>>(
        h, W1, b1, nullptr, u, P_, E_);
    gemm128_kernel<true, true, false><<<dim3(E_ / 128, M_ / 128), 256>>>(
        u, W2, b2, x2, out, E_, P_);
}

// round 3
// speedup vs baseline: 2.6946x; 2.6946x over previous
#include <cuda_runtime.h>
#include <cuda_bf16.h>
#include <cstdint>

#define B_  64
#define T_  320
#define E_  1024
#define H_  16
#define P_  4096
#define M_  (B_ * T_)          // 20480 tokens
#define EPS 1e-5f
#define SCALE 0.03125f          // E^-0.5

typedef unsigned u32;
typedef __nv_bfloat16 bf16;

// ---------------- scratch (device globals) ----------------
__device__ bf16 g_h_hi[(size_t)M_ * E_];
__device__ bf16 g_h_lo[(size_t)M_ * E_];
__device__ bf16 g_w3_hi[(size_t)E_ * 3 * E_];
__device__ bf16 g_w3_lo[(size_t)E_ * 3 * E_];
__device__ bf16 g_wo_hi[(size_t)E_ * E_];
__device__ bf16 g_wo_lo[(size_t)E_ * E_];
__device__ bf16 g_w1_hi[(size_t)E_ * P_];
__device__ bf16 g_w1_lo[(size_t)E_ * P_];
__device__ bf16 g_w2_hi[(size_t)P_ * E_];
__device__ bf16 g_w2_lo[(size_t)P_ * E_];
__device__ float g_qkv[(size_t)M_ * 3 * E_];
__device__ bf16 g_attn_hi[(size_t)M_ * E_];
__device__ bf16 g_attn_lo[(size_t)M_ * E_];
__device__ float g_x2[(size_t)M_ * E_];
__device__ bf16 g_u_hi[(size_t)M_ * P_];
__device__ bf16 g_u_lo[(size_t)M_ * P_];

// ---------------- helpers ----------------
__device__ __forceinline__ void split1(float x, bf16& h, bf16& l) {
    h = __float2bfloat16_rn(x);
    l = __float2bfloat16_rn(x - __bfloat162float(h));
}

__device__ __forceinline__ void split_store4(float4 v, bf16* hi, bf16* lo, size_t idx) {
    union { bf16 b[4]; uint2 u; } H, L;
    split1(v.x, H.b[0], L.b[0]);
    split1(v.y, H.b[1], L.b[1]);
    split1(v.z, H.b[2], L.b[2]);
    split1(v.w, H.b[3], L.b[3]);
    *(uint2*)(hi + idx) = H.u;
    *(uint2*)(lo + idx) = L.u;
}

__device__ __forceinline__ u32 smem_u32(const void* p) {
    return (u32)__cvta_generic_to_shared(p);
}

__device__ __forceinline__ void cp16(u32 dst, const void* src) {
    asm volatile("cp.async.cg.shared.global [%0], [%1], 16;" :: "r"(dst), "l"(src));
}
__device__ __forceinline__ void cp_commit() { asm volatile("cp.async.commit_group;"); }
__device__ __forceinline__ void cp_wait0() { asm volatile("cp.async.wait_group 0;"); }

__device__ __forceinline__ void ldsm4(u32 addr, u32& r0, u32& r1, u32& r2, u32& r3) {
    asm volatile("ldmatrix.sync.aligned.m8n8.x4.shared.b16 {%0,%1,%2,%3}, [%4];"
                 : "=r"(r0), "=r"(r1), "=r"(r2), "=r"(r3) : "r"(addr));
}
__device__ __forceinline__ void ldsm2t(u32 addr, u32& r0, u32& r1) {
    asm volatile("ldmatrix.sync.aligned.m8n8.x2.trans.shared.b16 {%0,%1}, [%2];"
                 : "=r"(r0), "=r"(r1) : "r"(addr));
}
__device__ __forceinline__ void mma_bf(float* c, const u32* a, const u32* b) {
    asm volatile("mma.sync.aligned.m16n8k16.row.col.f32.bf16.bf16.f32 "
                 "{%0,%1,%2,%3}, {%4,%5,%6,%7}, {%8,%9}, {%0,%1,%2,%3};"
                 : "+f"(c[0]), "+f"(c[1]), "+f"(c[2]), "+f"(c[3])
                 : "r"(a[0]), "r"(a[1]), "r"(a[2]), "r"(a[3]), "r"(b[0]), "r"(b[1]));
}

// ---------------- weight prep ----------------
__global__ void pack_w3_kernel(const float* __restrict__ Wq, const float* __restrict__ Wk,
                               const float* __restrict__ Wv, bf16* __restrict__ hi,
                               bf16* __restrict__ lo) {
    int idx = blockIdx.x * 256 + threadIdx.x;
    int k = idx / 3072, n = idx % 3072;
    int which = n >> 10, rem = n & 1023, hh = rem >> 6, d = rem & 63;
    const float* W = (which == 0) ? Wq : (which == 1) ? Wk : Wv;
    float v = W[(size_t)hh * E_ * 64 + (size_t)k * 64 + d];
    split1(v, hi[idx], lo[idx]);
}

__global__ void split_w_kernel(const float* __restrict__ src, bf16* __restrict__ hi,
                               bf16* __restrict__ lo, int n) {
    int idx = blockIdx.x * 256 + threadIdx.x;
    if (idx < n) split1(src[idx], hi[idx], lo[idx]);
}

// ---------------- layernorm (emits split bf16) ----------------
__device__ __forceinline__ float blockSum256(float v, float* sh) {
    __syncthreads();
    #pragma unroll
    for (int o = 16; o > 0; o >>= 1) v += __shfl_xor_sync(0xffffffffu, v, o);
    if ((threadIdx.x & 31) == 0) sh[threadIdx.x >> 5] = v;
    __syncthreads();
    if (threadIdx.x < 32) {
        float t = (threadIdx.x < 8) ? sh[threadIdx.x] : 0.0f;
        #pragma unroll
        for (int o = 4; o > 0; o >>= 1) t += __shfl_xor_sync(0xffffffffu, t, o);
        if (threadIdx.x == 0) sh[0] = t;
    }
    __syncthreads();
    return sh[0];
}

__global__ void ln_kernel(const float* __restrict__ x, const float* __restrict__ w,
                          const float* __restrict__ bb, bf16* __restrict__ hi,
                          bf16* __restrict__ lo) {
    __shared__ float sh[8];
    size_t row = blockIdx.x;
    int tid = threadIdx.x;
    const float4 v = ((const float4*)(x + row * E_))[tid];
    float s = v.x + v.y + v.z + v.w;
    s = blockSum256(s, sh);
    float mu = s * (1.0f / E_);
    float dx = v.x - mu, dy = v.y - mu, dz = v.z - mu, dw = v.w - mu;
    float ss = dx * dx + dy * dy + dz * dz + dw * dw;
    ss = blockSum256(ss, sh);
    float inv = rsqrtf(ss * (1.0f / E_) + EPS);
    float4 w4 = ((const float4*)w)[tid];
    float4 b4 = ((const float4*)bb)[tid];
    float4 r;
    r.x = dx * inv * w4.x + b4.x;
    r.y = dy * inv * w4.y + b4.y;
    r.z = dz * inv * w4.z + b4.z;
    r.w = dw * inv * w4.w + b4.w;
    split_store4(r, hi, lo, row * E_ + tid * 4);
}

// ---------------- split-bf16 tensor-core GEMM ----------------
// CTA 128x128, K-stage 32. smem: A[128][40]bf16 (80B pitch), B[32][136]bf16 (272B pitch)
#define A_BYTES 10240
#define B_BYTES 8704
#define STAGE_BYTES (2 * A_BYTES + 2 * B_BYTES)   // 37888
#define SM_TOTAL (2 * STAGE_BYTES)                 // 75776

template <bool BIAS, bool RESID, bool RELU, bool SPLITOUT>
__global__ __launch_bounds__(256, 2) void gemm_mma_kernel(
    const bf16* __restrict__ Ahi, const bf16* __restrict__ Alo,
    const bf16* __restrict__ Bhi, const bf16* __restrict__ Blo,
    const float* __restrict__ bias, const float* __restrict__ Rm,
    float* __restrict__ Cf, bf16* __restrict__ Chi, bf16* __restrict__ Clo,
    int N, int K) {
    extern __shared__ char sm[];
    const u32 smb = smem_u32(sm);

    int tid = threadIdx.x;
    int lane = tid & 31, wid = tid >> 5;
    int warpM = (wid >> 2) * 64, warpN = (wid & 3) * 32;
    int bm = blockIdx.y * 128, bn = blockIdx.x * 128;

    // global src element offsets (per thread, 2x16B chunks each array)
    size_t a_src = (size_t)(bm + (tid >> 1)) * K + (tid & 1) * 16;
    size_t b_src = (size_t)(tid >> 3) * N + bn + (tid & 7) * 16;
    u32 a_dst = (tid >> 1) * 80 + (tid & 1) * 32;
    u32 b_dst = (tid >> 3) * 272 + (tid & 7) * 32;

    // ldmatrix address components
    int a_row = warpM + (lane & 7) + ((lane >> 3) & 1) * 8;
    u32 a_off = a_row * 80 + (lane >> 4) * 16;
    u32 b_off = (lane & 15) * 272 + warpN * 2;

    float acc[4][4][4];
    #pragma unroll
    for (int i = 0; i < 4; i++)
        #pragma unroll
        for (int j = 0; j < 4; j++)
            #pragma unroll
            for (int c = 0; c < 4; c++) acc[i][j][c] = 0.0f;

    const int nk = K >> 5;

    // prologue: stage 0
    {
        u32 sb = smb;
        #pragma unroll
        for (int c = 0; c < 2; c++) {
            cp16(sb + a_dst + c * 16, Ahi + a_src + c * 8);
            cp16(sb + A_BYTES + a_dst + c * 16, Alo + a_src + c * 8);
            cp16(sb + 2 * A_BYTES + b_dst + c * 16, Bhi + b_src + c * 8);
            cp16(sb + 2 * A_BYTES + B_BYTES + b_dst + c * 16, Blo + b_src + c * 8);
        }
        cp_commit();
    }

    for (int kt = 0; kt < nk; kt++) {
        cp_wait0();
        __syncthreads();
        u32 cur = smb + (kt & 1) * STAGE_BYTES;

        if (kt + 1 < nk) {
            u32 nb = smb + ((kt + 1) & 1) * STAGE_BYTES;
            size_t ak = a_src + (size_t)(kt + 1) * 32;
            size_t bk = b_src + (size_t)(kt + 1) * 32 * N;
            #pragma unroll
            for (int c = 0; c < 2; c++) {
                cp16(nb + a_dst + c * 16, Ahi + ak + c * 8);
                cp16(nb + A_BYTES + a_dst + c * 16, Alo + ak + c * 8);
                cp16(nb + 2 * A_BYTES + b_dst + c * 16, Bhi + bk + c * 8);
                cp16(nb + 2 * A_BYTES + B_BYTES + b_dst + c * 16, Blo + bk + c * 8);
            }
            cp_commit();
        }

        #pragma unroll
        for (int ks = 0; ks < 2; ks++) {
            u32 bh[4][2], bl[4][2];
            #pragma unroll
            for (int ni = 0; ni < 4; ni++) {
                u32 ba = cur + 2 * A_BYTES + b_off + ni * 16 + ks * 4352;
                ldsm2t(ba, bh[ni][0], bh[ni][1]);
                ldsm2t(ba + B_BYTES, bl[ni][0], bl[ni][1]);
            }
            #pragma unroll
            for (int mi = 0; mi < 4; mi++) {
                u32 ah[4], al[4];
                u32 aa = cur + a_off + mi * 1280 + ks * 32;
                ldsm4(aa, ah[0], ah[1], ah[2], ah[3]);
                ldsm4(aa + A_BYTES, al[0], al[1], al[2], al[3]);
                #pragma unroll
                for (int ni = 0; ni < 4; ni++) {
                    mma_bf(acc[mi][ni], ah, bh[ni]);
                    mma_bf(acc[mi][ni], ah, bl[ni]);
                    mma_bf(acc[mi][ni], al, bh[ni]);
                }
            }
        }
    }

    // epilogue
    int g = lane >> 2, tg = lane & 3;
    #pragma unroll
    for (int mi = 0; mi < 4; mi++) {
        #pragma unroll
        for (int ni = 0; ni < 4; ni++) {
            int col = bn + warpN + ni * 8 + tg * 2;
            #pragma unroll
            for (int half = 0; half < 2; half++) {
                int row = bm + warpM + mi * 16 + g + half * 8;
                float vx = acc[mi][ni][half * 2 + 0];
                float vy = acc[mi][ni][half * 2 + 1];
                if (BIAS) {
                    float2 bb = *(const float2*)(bias + col);
                    vx += bb.x; vy += bb.y;
                }
                size_t off = (size_t)row * N + col;
                if (RESID) {
                    float2 rr = *(const float2*)(Rm + off);
                    vx += rr.x; vy += rr.y;
                }
                if (RELU) { vx = fmaxf(vx, 0.0f); vy = fmaxf(vy, 0.0f); }
                if (SPLITOUT) {
                    union { bf16 b[2]; u32 u; } H, L;
                    split1(vx, H.b[0], L.b[0]);
                    split1(vy, H.b[1], L.b[1]);
                    *(u32*)(Chi + off) = H.u;
                    *(u32*)(Clo + off) = L.u;
                } else {
                    float2 o; o.x = vx; o.y = vy;
                    *(float2*)(Cf + off) = o;
                }
            }
        }
    }
}

// ---------------- flash attention (fp32 SIMT, split-bf16 output) ----------------
#define APAD 68
__global__ __launch_bounds__(256) void attn_kernel(const float* __restrict__ qkv,
                                                   bf16* __restrict__ ohi,
                                                   bf16* __restrict__ olo) {
    extern __shared__ float smf[];
    float* Qt  = smf;
    float* Kst = smf + 64 * APAD;
    float* Vs  = smf + 2 * 64 * APAD;
    float* St  = smf + 3 * 64 * APAD;

    int qt = blockIdx.x, h = blockIdx.y, b = blockIdx.z;
    int tid = threadIdx.x, tx = tid & 15, ty = tid >> 4;
    int t0 = qt * 64;
    size_t base = (size_t)b * T_ * 3072;

    #pragma unroll
    for (int l = 0; l < 4; l++) {
        int idx = l * 256 + tid;
        int r = idx >> 4, d4 = (idx & 15) * 4;
        float4 v = *(const float4*)(qkv + base + (size_t)(t0 + r) * 3072 + h * 64 + d4);
        Qt[(d4 + 0) * APAD + r] = v.x;
        Qt[(d4 + 1) * APAD + r] = v.y;
        Qt[(d4 + 2) * APAD + r] = v.z;
        Qt[(d4 + 3) * APAD + r] = v.w;
    }

    float o[4][4], m[4], l_[4];
    #pragma unroll
    for (int i = 0; i < 4; i++) {
        m[i] = -1e30f; l_[i] = 0.0f;
        #pragma unroll
        for (int j = 0; j < 4; j++) o[i][j] = 0.0f;
    }

    for (int ktile = 0; ktile <= qt; ++ktile) {
        __syncthreads();
        int k0 = ktile * 64;
        #pragma unroll
        for (int l = 0; l < 4; l++) {
            int idx = l * 256 + tid;
            int r = idx >> 4, d4 = (idx & 15) * 4;
            float4 kv = *(const float4*)(qkv + base + (size_t)(k0 + r) * 3072 + 1024 + h * 64 + d4);
            Kst[(d4 + 0) * APAD + r] = kv.x;
            Kst[(d4 + 1) * APAD + r] = kv.y;
            Kst[(d4 + 2) * APAD + r] = kv.z;
            Kst[(d4 + 3) * APAD + r] = kv.w;
            float4 vv = *(const float4*)(qkv + base + (size_t)(k0 + r) * 3072 + 2048 + h * 64 + d4);
            *(float4*)&Vs[r * APAD + d4] = vv;
        }
        __syncthreads();

        float s[4][4];
        #pragma unroll
        for (int i = 0; i < 4; i++)
            #pragma unroll
            for (int j = 0; j < 4; j++) s[i][j] = 0.0f;

        for (int d = 0; d < 64; d++) {
            float4 a = *(float4*)&Qt[d * APAD + ty * 4];
            float4 c = *(float4*)&Kst[d * APAD + tx * 4];
            float av[4] = {a.x, a.y, a.z, a.w};
            float cv[4] = {c.x, c.y, c.z, c.w};
            #pragma unroll
            for (int i = 0; i < 4; i++)
                #pragma unroll
                for (int j = 0; j < 4; j++) s[i][j] += av[i] * cv[j];
        }
        #pragma unroll
        for (int i = 0; i < 4; i++)
            #pragma unroll
            for (int j = 0; j < 4; j++) s[i][j] *= SCALE;

        if (ktile == qt) {
            #pragma unroll
            for (int i = 0; i < 4; i++)
                #pragma unroll
                for (int j = 0; j < 4; j++)
                    if (k0 + tx * 4 + j > t0 + ty * 4 + i) s[i][j] = -1e30f;
        }

        #pragma unroll
        for (int i = 0; i < 4; i++) {
            float mx = fmaxf(fmaxf(s[i][0], s[i][1]), fmaxf(s[i][2], s[i][3]));
            #pragma unroll
            for (int off = 8; off > 0; off >>= 1)
                mx = fmaxf(mx, __shfl_xor_sync(0xffffffffu, mx, off, 16));
            float mn = fmaxf(m[i], mx);
            float al = __expf(m[i] - mn);
            float rs = 0.0f;
            #pragma unroll
            for (int j = 0; j < 4; j++) {
                float p = __expf(s[i][j] - mn);
                s[i][j] = p;
                rs += p;
            }
            #pragma unroll
            for (int off = 8; off > 0; off >>= 1)
                rs += __shfl_xor_sync(0xffffffffu, rs, off, 16);
            l_[i] = l_[i] * al + rs;
            m[i] = mn;
            #pragma unroll
            for (int j = 0; j < 4; j++) o[i][j] *= al;
            #pragma unroll
            for (int j = 0; j < 4; j++)
                St[(tx * 4 + j) * APAD + ty * 4 + i] = s[i][j];
        }
        __syncthreads();

        for (int kc = 0; kc < 64; kc++) {
            float4 a = *(float4*)&St[kc * APAD + ty * 4];
            float4 vv = *(float4*)&Vs[kc * APAD + tx * 4];
            float av[4] = {a.x, a.y, a.z, a.w};
            float bv[4] = {vv.x, vv.y, vv.z, vv.w};
            #pragma unroll
            for (int i = 0; i < 4; i++)
                #pragma unroll
                for (int j = 0; j < 4; j++) o[i][j] += av[i] * bv[j];
        }
    }

    #pragma unroll
    for (int i = 0; i < 4; i++) {
        float inv = 1.0f / l_[i];
        float4 v;
        v.x = o[i][0] * inv; v.y = o[i][1] * inv;
        v.z = o[i][2] * inv; v.w = o[i][3] * inv;
        split_store4(v, ohi, olo,
                     ((size_t)b * T_ + t0 + ty * 4 + i) * E_ + h * 64 + tx * 4);
    }
}

// ---------------- launch ----------------
extern "C" void kernel_launch(void* const* d_in, const int* in_sizes, int n_in,
                              void* d_out, int out_size) {
    const float* x    = (const float*)d_in[0];
    const float* Wq   = (const float*)d_in[1];
    const float* Wk   = (const float*)d_in[2];
    const float* Wv   = (const float*)d_in[3];
    const float* Wo   = (const float*)d_in[4];
    const float* bo   = (const float*)d_in[5];
    const float* W1   = (const float*)d_in[6];
    const float* b1   = (const float*)d_in[7];
    const float* W2   = (const float*)d_in[8];
    const float* b2   = (const float*)d_in[9];
    const float* ln1w = (const float*)d_in[10];
    const float* ln1b = (const float*)d_in[11];
    const float* ln2w = (const float*)d_in[12];
    const float* ln2b = (const float*)d_in[13];
    float* out = (float*)d_out;

    bf16 *h_hi, *h_lo, *w3_hi, *w3_lo, *wo_hi, *wo_lo, *w1_hi, *w1_lo, *w2_hi, *w2_lo;
    bf16 *attn_hi, *attn_lo, *u_hi, *u_lo;
    float *qkv, *x2;
    cudaGetSymbolAddress((void**)&h_hi, g_h_hi);
    cudaGetSymbolAddress((void**)&h_lo, g_h_lo);
    cudaGetSymbolAddress((void**)&w3_hi, g_w3_hi);
    cudaGetSymbolAddress((void**)&w3_lo, g_w3_lo);
    cudaGetSymbolAddress((void**)&wo_hi, g_wo_hi);
    cudaGetSymbolAddress((void**)&wo_lo, g_wo_lo);
    cudaGetSymbolAddress((void**)&w1_hi, g_w1_hi);
    cudaGetSymbolAddress((void**)&w1_lo, g_w1_lo);
    cudaGetSymbolAddress((void**)&w2_hi, g_w2_hi);
    cudaGetSymbolAddress((void**)&w2_lo, g_w2_lo);
    cudaGetSymbolAddress((void**)&qkv, g_qkv);
    cudaGetSymbolAddress((void**)&attn_hi, g_attn_hi);
    cudaGetSymbolAddress((void**)&attn_lo, g_attn_lo);
    cudaGetSymbolAddress((void**)&x2, g_x2);
    cudaGetSymbolAddress((void**)&u_hi, g_u_hi);
    cudaGetSymbolAddress((void**)&u_lo, g_u_lo);

    cudaFuncSetAttribute(attn_kernel, cudaFuncAttributeMaxDynamicSharedMemorySize,
                         4 * 64 * APAD * 4);
    cudaFuncSetAttribute(gemm_mma_kernel<false, false, false, false>,
                         cudaFuncAttributeMaxDynamicSharedMemorySize, SM_TOTAL);
    cudaFuncSetAttribute(gemm_mma_kernel<true, true, false, false>,
                         cudaFuncAttributeMaxDynamicSharedMemorySize, SM_TOTAL);
    cudaFuncSetAttribute(gemm_mma_kernel<true, false, true, true>,
                         cudaFuncAttributeMaxDynamicSharedMemorySize, SM_TOTAL);

    // weight prep
    pack_w3_kernel<<<(3 * E_ * E_) / 256, 256>>>(Wq, Wk, Wv, w3_hi, w3_lo);
    split_w_kernel<<<(E_ * E_) / 256, 256>>>(Wo, wo_hi, wo_lo, E_ * E_);
    split_w_kernel<<<(E_ * P_) / 256, 256>>>(W1, w1_hi, w1_lo, E_ * P_);
    split_w_kernel<<<(P_ * E_) / 256, 256>>>(W2, w2_hi, w2_lo, P_ * E_);

    // LN1
    ln_kernel<<<M_, 256>>>(x, ln1w, ln1b, h_hi, h_lo);

    // QKV: [M,1024] @ [1024,3072] -> fp32
    gemm_mma_kernel<false, false, false, false><<<dim3(3072 / 128, M_ / 128), 256, SM_TOTAL>>>(
        h_hi, h_lo, w3_hi, w3_lo, nullptr, nullptr, qkv, nullptr, nullptr, 3072, E_);

    // attention
    attn_kernel<<<dim3(T_ / 64, H_, B_), 256, 4 * 64 * APAD * 4>>>(qkv, attn_hi, attn_lo);

    // out-proj + bias + residual(x) -> fp32 x2
    gemm_mma_kernel<true, true, false, false><<<dim3(E_ / 128, M_ / 128), 256, SM_TOTAL>>>(
        attn_hi, attn_lo, wo_hi, wo_lo, bo, x, x2, nullptr, nullptr, E_, E_);

    // LN2
    ln_kernel<<<M_, 256>>>(x2, ln2w, ln2b, h_hi, h_lo);

    // FFN1: relu(h @ W1 + b1) -> split bf16 u
    gemm_mma_kernel<true, false, true, true><<<dim3(P_ / 128, M_ / 128), 256, SM_TOTAL>>>(
        h_hi, h_lo, w1_hi, w1_lo, b1, nullptr, nullptr, u_hi, u_lo, P_, E_);

    // FFN2: x2 + u @ W2 + b2 -> out fp32
    gemm_mma_kernel<true, true, false, false><<<dim3(E_ / 128, M_ / 128), 256, SM_TOTAL>>>(
        u_hi, u_lo, w2_hi, w2_lo, b2, x2, out, nullptr, nullptr, E_, P_);
}

// round 5
// speedup vs baseline: 3.5491x; 1.3171x over previous
#include <cuda_runtime.h>
#include <cuda_fp16.h>
#include <cstdint>

#define B_  64
#define T_  320
#define E_  1024
#define H_  16
#define P_  4096
#define M_  (B_ * T_)          // 20480 tokens
#define EPS 1e-5f
#define SCALE 0.03125f          // E^-0.5

typedef unsigned u32;
typedef __half fp16;

// ---------------- scratch (device globals) ----------------
__device__ fp16 g_h_hi[(size_t)M_ * E_];
__device__ fp16 g_h_lo[(size_t)M_ * E_];
__device__ fp16 g_w3[(size_t)E_ * 3 * E_];      // [K=1024][N=3072]
__device__ fp16 g_wo[(size_t)E_ * E_];          // [K][N]
__device__ fp16 g_w1[(size_t)E_ * P_];          // [K=1024][N=4096]
__device__ fp16 g_w2[(size_t)P_ * E_];          // [K=4096][N=1024]
__device__ float g_qkv[(size_t)M_ * 3 * E_];
__device__ fp16 g_attn_hi[(size_t)M_ * E_];
__device__ fp16 g_attn_lo[(size_t)M_ * E_];
__device__ float g_x2[(size_t)M_ * E_];
__device__ fp16 g_u_hi[(size_t)M_ * P_];
__device__ fp16 g_u_lo[(size_t)M_ * P_];

// ---------------- helpers ----------------
__device__ __forceinline__ void split1(float x, fp16& h, fp16& l) {
    h = __float2half_rn(x);
    l = __float2half_rn(x - __half2float(h));
}
__device__ __forceinline__ void split_store4(float4 v, fp16* hi, fp16* lo, size_t idx) {
    union { fp16 b[4]; uint2 u; } Hx, Lx;
    split1(v.x, Hx.b[0], Lx.b[0]);
    split1(v.y, Hx.b[1], Lx.b[1]);
    split1(v.z, Hx.b[2], Lx.b[2]);
    split1(v.w, Hx.b[3], Lx.b[3]);
    *(uint2*)(hi + idx) = Hx.u;
    *(uint2*)(lo + idx) = Lx.u;
}
__device__ __forceinline__ u32 smem_u32(const void* p) {
    return (u32)__cvta_generic_to_shared(p);
}
__device__ __forceinline__ void cp16(u32 dst, const void* src) {
    asm volatile("cp.async.cg.shared.global [%0], [%1], 16;" :: "r"(dst), "l"(src));
}
__device__ __forceinline__ void cp_commit() { asm volatile("cp.async.commit_group;"); }
__device__ __forceinline__ void cp_wait0() { asm volatile("cp.async.wait_group 0;"); }

__device__ __forceinline__ void ldsm4(u32 addr, u32& r0, u32& r1, u32& r2, u32& r3) {
    asm volatile("ldmatrix.sync.aligned.m8n8.x4.shared.b16 {%0,%1,%2,%3}, [%4];"
                 : "=r"(r0), "=r"(r1), "=r"(r2), "=r"(r3) : "r"(addr));
}
__device__ __forceinline__ void ldsm2t(u32 addr, u32& r0, u32& r1) {
    asm volatile("ldmatrix.sync.aligned.m8n8.x2.trans.shared.b16 {%0,%1}, [%2];"
                 : "=r"(r0), "=r"(r1) : "r"(addr));
}
__device__ __forceinline__ void mma_fp16(float* c, const u32* a, const u32* b) {
    asm volatile("mma.sync.aligned.m16n8k16.row.col.f32.f16.f16.f32 "
                 "{%0,%1,%2,%3}, {%4,%5,%6,%7}, {%8,%9}, {%0,%1,%2,%3};"
                 : "+f"(c[0]), "+f"(c[1]), "+f"(c[2]), "+f"(c[3])
                 : "r"(a[0]), "r"(a[1]), "r"(a[2]), "r"(a[3]), "r"(b[0]), "r"(b[1]));
}

// ---------------- weight prep ----------------
__global__ void pack_w3_kernel(const float* __restrict__ Wq, const float* __restrict__ Wk,
                               const float* __restrict__ Wv, fp16* __restrict__ w) {
    int idx = blockIdx.x * 256 + threadIdx.x;
    int k = idx / 3072, n = idx % 3072;
    int which = n >> 10, rem = n & 1023, hh = rem >> 6, d = rem & 63;
    const float* W = (which == 0) ? Wq : (which == 1) ? Wk : Wv;
    w[idx] = __float2half_rn(W[(size_t)hh * E_ * 64 + (size_t)k * 64 + d]);
}

__global__ void quant_w_kernel(const float* __restrict__ src, fp16* __restrict__ dst, int n) {
    int idx = blockIdx.x * 256 + threadIdx.x;
    if (idx < n) dst[idx] = __float2half_rn(src[idx]);
}

// ---------------- layernorm (emits split fp16) ----------------
__device__ __forceinline__ float blockSum256(float v, float* sh) {
    __syncthreads();
    #pragma unroll
    for (int o = 16; o > 0; o >>= 1) v += __shfl_xor_sync(0xffffffffu, v, o);
    if ((threadIdx.x & 31) == 0) sh[threadIdx.x >> 5] = v;
    __syncthreads();
    if (threadIdx.x < 32) {
        float t = (threadIdx.x < 8) ? sh[threadIdx.x] : 0.0f;
        #pragma unroll
        for (int o = 4; o > 0; o >>= 1) t += __shfl_xor_sync(0xffffffffu, t, o);
        if (threadIdx.x == 0) sh[0] = t;
    }
    __syncthreads();
    return sh[0];
}

__global__ void ln_kernel(const float* __restrict__ x, const float* __restrict__ w,
                          const float* __restrict__ bb, fp16* __restrict__ hi,
                          fp16* __restrict__ lo) {
    __shared__ float sh[8];
    size_t row = blockIdx.x;
    int tid = threadIdx.x;
    const float4 v = ((const float4*)(x + row * E_))[tid];
    float s = v.x + v.y + v.z + v.w;
    s = blockSum256(s, sh);
    float mu = s * (1.0f / E_);
    float dx = v.x - mu, dy = v.y - mu, dz = v.z - mu, dw = v.w - mu;
    float ss = dx * dx + dy * dy + dz * dz + dw * dw;
    ss = blockSum256(ss, sh);
    float inv = rsqrtf(ss * (1.0f / E_) + EPS);
    float4 w4 = ((const float4*)w)[tid];
    float4 b4 = ((const float4*)bb)[tid];
    float4 r;
    r.x = dx * inv * w4.x + b4.x;
    r.y = dy * inv * w4.y + b4.y;
    r.z = dz * inv * w4.z + b4.z;
    r.w = dw * inv * w4.w + b4.w;
    split_store4(r, hi, lo, row * E_ + tid * 4);
}

// ---------------- 2-pass fp16 tensor-core GEMM ----------------
// CTA 128x128, K-stage 32. smem: Ahi[128][40], Alo[128][40] (80B pitch), B[32][136] (272B pitch)
#define A_BYTES 10240
#define B_BYTES 8704
#define STAGE_BYTES (2 * A_BYTES + B_BYTES)    // 29184
#define SM_TOTAL (2 * STAGE_BYTES)             // 58368

template <bool BIAS, bool RESID, bool RELU, bool SPLITOUT>
__global__ __launch_bounds__(256, 2) void gemm_mma_kernel(
    const fp16* __restrict__ Ahi, const fp16* __restrict__ Alo,
    const fp16* __restrict__ Bw,
    const float* __restrict__ bias, const float* __restrict__ Rm,
    float* __restrict__ Cf, fp16* __restrict__ Chi, fp16* __restrict__ Clo,
    int N, int K) {
    extern __shared__ char sm[];
    const u32 smb = smem_u32(sm);

    int tid = threadIdx.x;
    int lane = tid & 31, wid = tid >> 5;
    int warpM = (wid >> 2) * 64, warpN = (wid & 3) * 32;
    int bm = blockIdx.y * 128, bn = blockIdx.x * 128;

    size_t a_src = (size_t)(bm + (tid >> 1)) * K + (tid & 1) * 16;
    size_t b_src = (size_t)(tid >> 3) * N + bn + (tid & 7) * 16;
    u32 a_dst = (tid >> 1) * 80 + (tid & 1) * 32;
    u32 b_dst = (tid >> 3) * 272 + (tid & 7) * 32;

    int a_row = warpM + (lane & 7) + ((lane >> 3) & 1) * 8;
    u32 a_off = a_row * 80 + (lane >> 4) * 16;
    u32 b_off = (lane & 15) * 272 + warpN * 2;

    float acc[4][4][4];
    #pragma unroll
    for (int i = 0; i < 4; i++)
        #pragma unroll
        for (int j = 0; j < 4; j++)
            #pragma unroll
            for (int c = 0; c < 4; c++) acc[i][j][c] = 0.0f;

    const int nk = K >> 5;

    // prologue: stage 0
    {
        u32 sb = smb;
        #pragma unroll
        for (int c = 0; c < 2; c++) {
            cp16(sb + a_dst + c * 16, Ahi + a_src + c * 8);
            cp16(sb + A_BYTES + a_dst + c * 16, Alo + a_src + c * 8);
            cp16(sb + 2 * A_BYTES + b_dst + c * 16, Bw + b_src + c * 8);
        }
        cp_commit();
    }

    for (int kt = 0; kt < nk; kt++) {
        cp_wait0();
        __syncthreads();
        u32 cur = smb + (kt & 1) * STAGE_BYTES;

        if (kt + 1 < nk) {
            u32 nb = smb + ((kt + 1) & 1) * STAGE_BYTES;
            size_t ak = a_src + (size_t)(kt + 1) * 32;
            size_t bk = b_src + (size_t)(kt + 1) * 32 * N;
            #pragma unroll
            for (int c = 0; c < 2; c++) {
                cp16(nb + a_dst + c * 16, Ahi + ak + c * 8);
                cp16(nb + A_BYTES + a_dst + c * 16, Alo + ak + c * 8);
                cp16(nb + 2 * A_BYTES + b_dst + c * 16, Bw + bk + c * 8);
            }
            cp_commit();
        }

        #pragma unroll
        for (int ks = 0; ks < 2; ks++) {
            u32 bw[4][2];
            #pragma unroll
            for (int ni = 0; ni < 4; ni++) {
                u32 ba = cur + 2 * A_BYTES + b_off + ni * 16 + ks * 4352;
                ldsm2t(ba, bw[ni][0], bw[ni][1]);
            }
            #pragma unroll
            for (int mi = 0; mi < 4; mi++) {
                u32 ah[4], al[4];
                u32 aa = cur + a_off + mi * 1280 + ks * 32;
                ldsm4(aa, ah[0], ah[1], ah[2], ah[3]);
                ldsm4(aa + A_BYTES, al[0], al[1], al[2], al[3]);
                #pragma unroll
                for (int ni = 0; ni < 4; ni++) {
                    mma_fp16(acc[mi][ni], ah, bw[ni]);
                    mma_fp16(acc[mi][ni], al, bw[ni]);
                }
            }
        }
    }

    // epilogue
    int g = lane >> 2, tg = lane & 3;
    #pragma unroll
    for (int mi = 0; mi < 4; mi++) {
        #pragma unroll
        for (int ni = 0; ni < 4; ni++) {
            int col = bn + warpN + ni * 8 + tg * 2;
            #pragma unroll
            for (int half = 0; half < 2; half++) {
                int row = bm + warpM + mi * 16 + g + half * 8;
                float vx = acc[mi][ni][half * 2 + 0];
                float vy = acc[mi][ni][half * 2 + 1];
                if (BIAS) {
                    float2 bb = *(const float2*)(bias + col);
                    vx += bb.x; vy += bb.y;
                }
                size_t off = (size_t)row * N + col;
                if (RESID) {
                    float2 rr = *(const float2*)(Rm + off);
                    vx += rr.x; vy += rr.y;
                }
                if (RELU) { vx = fmaxf(vx, 0.0f); vy = fmaxf(vy, 0.0f); }
                if (SPLITOUT) {
                    union { fp16 b[2]; u32 u; } Hx, Lx;
                    split1(vx, Hx.b[0], Lx.b[0]);
                    split1(vy, Hx.b[1], Lx.b[1]);
                    *(u32*)(Chi + off) = Hx.u;
                    *(u32*)(Clo + off) = Lx.u;
                } else {
                    float2 o; o.x = vx; o.y = vy;
                    *(float2*)(Cf + off) = o;
                }
            }
        }
    }
}

// ---------------- flash attention (fp32 SIMT, split-fp16 output) ----------------
#define APAD 68
__global__ __launch_bounds__(256) void attn_kernel(const float* __restrict__ qkv,
                                                   fp16* __restrict__ ohi,
                                                   fp16* __restrict__ olo) {
    extern __shared__ float smf[];
    float* Qt  = smf;
    float* Kst = smf + 64 * APAD;
    float* Vs  = smf + 2 * 64 * APAD;
    float* St  = smf + 3 * 64 * APAD;

    int qt = blockIdx.x, h = blockIdx.y, b = blockIdx.z;
    int tid = threadIdx.x, tx = tid & 15, ty = tid >> 4;
    int t0 = qt * 64;
    size_t base = (size_t)b * T_ * 3072;

    #pragma unroll
    for (int l = 0; l < 4; l++) {
        int idx = l * 256 + tid;
        int r = idx >> 4, d4 = (idx & 15) * 4;
        float4 v = *(const float4*)(qkv + base + (size_t)(t0 + r) * 3072 + h * 64 + d4);
        Qt[(d4 + 0) * APAD + r] = v.x;
        Qt[(d4 + 1) * APAD + r] = v.y;
        Qt[(d4 + 2) * APAD + r] = v.z;
        Qt[(d4 + 3) * APAD + r] = v.w;
    }

    float o[4][4], m[4], l_[4];
    #pragma unroll
    for (int i = 0; i < 4; i++) {
        m[i] = -1e30f; l_[i] = 0.0f;
        #pragma unroll
        for (int j = 0; j < 4; j++) o[i][j] = 0.0f;
    }

    for (int ktile = 0; ktile <= qt; ++ktile) {
        __syncthreads();
        int k0 = ktile * 64;
        #pragma unroll
        for (int l = 0; l < 4; l++) {
            int idx = l * 256 + tid;
            int r = idx >> 4, d4 = (idx & 15) * 4;
            float4 kv = *(const float4*)(qkv + base + (size_t)(k0 + r) * 3072 + 1024 + h * 64 + d4);
            Kst[(d4 + 0) * APAD + r] = kv.x;
            Kst[(d4 + 1) * APAD + r] = kv.y;
            Kst[(d4 + 2) * APAD + r] = kv.z;
            Kst[(d4 + 3) * APAD + r] = kv.w;
            float4 vv = *(const float4*)(qkv + base + (size_t)(k0 + r) * 3072 + 2048 + h * 64 + d4);
            *(float4*)&Vs[r * APAD + d4] = vv;
        }
        __syncthreads();

        float s[4][4];
        #pragma unroll
        for (int i = 0; i < 4; i++)
            #pragma unroll
            for (int j = 0; j < 4; j++) s[i][j] = 0.0f;

        for (int d = 0; d < 64; d++) {
            float4 a = *(float4*)&Qt[d * APAD + ty * 4];
            float4 cc = *(float4*)&Kst[d * APAD + tx * 4];
            float av[4] = {a.x, a.y, a.z, a.w};
            float cv[4] = {cc.x, cc.y, cc.z, cc.w};
            #pragma unroll
            for (int i = 0; i < 4; i++)
                #pragma unroll
                for (int j = 0; j < 4; j++) s[i][j] += av[i] * cv[j];
        }
        #pragma unroll
        for (int i = 0; i < 4; i++)
            #pragma unroll
            for (int j = 0; j < 4; j++) s[i][j] *= SCALE;

        if (ktile == qt) {
            #pragma unroll
            for (int i = 0; i < 4; i++)
                #pragma unroll
                for (int j = 0; j < 4; j++)
                    if (k0 + tx * 4 + j > t0 + ty * 4 + i) s[i][j] = -1e30f;
        }

        #pragma unroll
        for (int i = 0; i < 4; i++) {
            float mx = fmaxf(fmaxf(s[i][0], s[i][1]), fmaxf(s[i][2], s[i][3]));
            #pragma unroll
            for (int off = 8; off > 0; off >>= 1)
                mx = fmaxf(mx, __shfl_xor_sync(0xffffffffu, mx, off, 16));
            float mn = fmaxf(m[i], mx);
            float al = __expf(m[i] - mn);
            float rs = 0.0f;
            #pragma unroll
            for (int j = 0; j < 4; j++) {
                float p = __expf(s[i][j] - mn);
                s[i][j] = p;
                rs += p;
            }
            #pragma unroll
            for (int off = 8; off > 0; off >>= 1)
                rs += __shfl_xor_sync(0xffffffffu, rs, off, 16);
            l_[i] = l_[i] * al + rs;
            m[i] = mn;
            #pragma unroll
            for (int j = 0; j < 4; j++) o[i][j] *= al;
            #pragma unroll
            for (int j = 0; j < 4; j++)
                St[(tx * 4 + j) * APAD + ty * 4 + i] = s[i][j];
        }
        __syncthreads();

        for (int kc = 0; kc < 64; kc++) {
            float4 a = *(float4*)&St[kc * APAD + ty * 4];
            float4 vv = *(float4*)&Vs[kc * APAD + tx * 4];
            float av[4] = {a.x, a.y, a.z, a.w};
            float bv[4] = {vv.x, vv.y, vv.z, vv.w};
            #pragma unroll
            for (int i = 0; i < 4; i++)
                #pragma unroll
                for (int j = 0; j < 4; j++) o[i][j] += av[i] * bv[j];
        }
    }

    #pragma unroll
    for (int i = 0; i < 4; i++) {
        float inv = 1.0f / l_[i];
        float4 v;
        v.x = o[i][0] * inv; v.y = o[i][1] * inv;
        v.z = o[i][2] * inv; v.w = o[i][3] * inv;
        split_store4(v, ohi, olo,
                     ((size_t)b * T_ + t0 + ty * 4 + i) * E_ + h * 64 + tx * 4);
    }
}

// ---------------- launch ----------------
extern "C" void kernel_launch(void* const* d_in, const int* in_sizes, int n_in,
                              void* d_out, int out_size) {
    const float* x    = (const float*)d_in[0];
    const float* Wq   = (const float*)d_in[1];
    const float* Wk   = (const float*)d_in[2];
    const float* Wv   = (const float*)d_in[3];
    const float* Wo   = (const float*)d_in[4];
    const float* bo   = (const float*)d_in[5];
    const float* W1   = (const float*)d_in[6];
    const float* b1   = (const float*)d_in[7];
    const float* W2   = (const float*)d_in[8];
    const float* b2   = (const float*)d_in[9];
    const float* ln1w = (const float*)d_in[10];
    const float* ln1b = (const float*)d_in[11];
    const float* ln2w = (const float*)d_in[12];
    const float* ln2b = (const float*)d_in[13];
    float* out = (float*)d_out;

    fp16 *h_hi, *h_lo, *w3, *wo, *w1, *w2, *attn_hi, *attn_lo, *u_hi, *u_lo;
    float *qkv, *x2;
    cudaGetSymbolAddress((void**)&h_hi, g_h_hi);
    cudaGetSymbolAddress((void**)&h_lo, g_h_lo);
    cudaGetSymbolAddress((void**)&w3, g_w3);
    cudaGetSymbolAddress((void**)&wo, g_wo);
    cudaGetSymbolAddress((void**)&w1, g_w1);
    cudaGetSymbolAddress((void**)&w2, g_w2);
    cudaGetSymbolAddress((void**)&qkv, g_qkv);
    cudaGetSymbolAddress((void**)&attn_hi, g_attn_hi);
    cudaGetSymbolAddress((void**)&attn_lo, g_attn_lo);
    cudaGetSymbolAddress((void**)&x2, g_x2);
    cudaGetSymbolAddress((void**)&u_hi, g_u_hi);
    cudaGetSymbolAddress((void**)&u_lo, g_u_lo);

    cudaFuncSetAttribute(attn_kernel, cudaFuncAttributeMaxDynamicSharedMemorySize,
                         4 * 64 * APAD * 4);
    cudaFuncSetAttribute(gemm_mma_kernel<false, false, false, false>,
                         cudaFuncAttributeMaxDynamicSharedMemorySize, SM_TOTAL);
    cudaFuncSetAttribute(gemm_mma_kernel<true, true, false, false>,
                         cudaFuncAttributeMaxDynamicSharedMemorySize, SM_TOTAL);
    cudaFuncSetAttribute(gemm_mma_kernel<true, false, true, true>,
                         cudaFuncAttributeMaxDynamicSharedMemorySize, SM_TOTAL);

    // weight prep (fp16 quantize, [K][N] layouts)
    pack_w3_kernel<<<(3 * E_ * E_) / 256, 256>>>(Wq, Wk, Wv, w3);
    quant_w_kernel<<<(E_ * E_) / 256, 256>>>(Wo, wo, E_ * E_);
    quant_w_kernel<<<(E_ * P_) / 256, 256>>>(W1, w1, E_ * P_);
    quant_w_kernel<<<(P_ * E_) / 256, 256>>>(W2, w2, P_ * E_);

    // LN1
    ln_kernel<<<M_, 256>>>(x, ln1w, ln1b, h_hi, h_lo);

    // QKV: [M,1024] @ [1024,3072] -> fp32
    gemm_mma_kernel<false, false, false, false><<<dim3(3072 / 128, M_ / 128), 256, SM_TOTAL>>>(
        h_hi, h_lo, w3, nullptr, nullptr, qkv, nullptr, nullptr, 3072, E_);

    // attention
    attn_kernel<<<dim3(T_ / 64, H_, B_), 256, 4 * 64 * APAD * 4>>>(qkv, attn_hi, attn_lo);

    // out-proj + bias + residual(x) -> fp32 x2
    gemm_mma_kernel<true, true, false, false><<<dim3(E_ / 128, M_ / 128), 256, SM_TOTAL>>>(
        attn_hi, attn_lo, wo, bo, x, x2, nullptr, nullptr, E_, E_);

    // LN2
    ln_kernel<<<M_, 256>>>(x2, ln2w, ln2b, h_hi, h_lo);

    // FFN1: relu(h @ W1 + b1) -> split fp16 u
    gemm_mma_kernel<true, false, true, true><<<dim3(P_ / 128, M_ / 128), 256, SM_TOTAL>>>(
        h_hi, h_lo, w1, b1, nullptr, nullptr, u_hi, u_lo, P_, E_);

    // FFN2: x2 + u @ W2 + b2 -> out fp32
    gemm_mma_kernel<true, true, false, false><<<dim3(E_ / 128, M_ / 128), 256, SM_TOTAL>>>(
        u_hi, u_lo, w2, b2, x2, out, nullptr, nullptr, E_, P_);
}

// round 6
// speedup vs baseline: 5.3275x; 1.5011x over previous
#include <cuda_runtime.h>
#include <cuda_fp16.h>
#include <cstdint>

#define B_  64
#define T_  320
#define E_  1024
#define H_  16
#define P_  4096
#define M_  (B_ * T_)          // 20480 tokens
#define EPS 1e-5f
#define SCALE 0.03125f          // E^-0.5

typedef unsigned u32;
typedef __half fp16;

// ---------------- scratch (device globals) ----------------
__device__ fp16 g_h[(size_t)M_ * E_];
__device__ fp16 g_w3[(size_t)E_ * 3 * E_];      // [K=1024][N=3072]
__device__ fp16 g_wo[(size_t)E_ * E_];          // [K][N]
__device__ fp16 g_w1[(size_t)E_ * P_];          // [K=1024][N=4096]
__device__ fp16 g_w2[(size_t)P_ * E_];          // [K=4096][N=1024]
__device__ float g_qkv[(size_t)M_ * 3 * E_];
__device__ fp16 g_attn[(size_t)M_ * E_];
__device__ float g_x2[(size_t)M_ * E_];
__device__ fp16 g_u[(size_t)M_ * P_];

// ---------------- helpers ----------------
__device__ __forceinline__ u32 smem_u32(const void* p) {
    return (u32)__cvta_generic_to_shared(p);
}
__device__ __forceinline__ void cp16(u32 dst, const void* src) {
    asm volatile("cp.async.cg.shared.global [%0], [%1], 16;" :: "r"(dst), "l"(src));
}
__device__ __forceinline__ void cp_commit() { asm volatile("cp.async.commit_group;"); }
__device__ __forceinline__ void cp_wait0() { asm volatile("cp.async.wait_group 0;"); }

__device__ __forceinline__ void ldsm4(u32 addr, u32& r0, u32& r1, u32& r2, u32& r3) {
    asm volatile("ldmatrix.sync.aligned.m8n8.x4.shared.b16 {%0,%1,%2,%3}, [%4];"
                 : "=r"(r0), "=r"(r1), "=r"(r2), "=r"(r3) : "r"(addr));
}
__device__ __forceinline__ void ldsm2t(u32 addr, u32& r0, u32& r1) {
    asm volatile("ldmatrix.sync.aligned.m8n8.x2.trans.shared.b16 {%0,%1}, [%2];"
                 : "=r"(r0), "=r"(r1) : "r"(addr));
}
__device__ __forceinline__ void mma_fp16(float* c, const u32* a, const u32* b) {
    asm volatile("mma.sync.aligned.m16n8k16.row.col.f32.f16.f16.f32 "
                 "{%0,%1,%2,%3}, {%4,%5,%6,%7}, {%8,%9}, {%0,%1,%2,%3};"
                 : "+f"(c[0]), "+f"(c[1]), "+f"(c[2]), "+f"(c[3])
                 : "r"(a[0]), "r"(a[1]), "r"(a[2]), "r"(a[3]), "r"(b[0]), "r"(b[1]));
}
__device__ __forceinline__ void h2store4(float4 v, fp16* dst, size_t idx) {
    union { __half2 h[2]; uint2 u; } P;
    P.h[0] = __floats2half2_rn(v.x, v.y);
    P.h[1] = __floats2half2_rn(v.z, v.w);
    *(uint2*)(dst + idx) = P.u;
}

// ---------------- weight prep ----------------
__global__ void pack_w3_kernel(const float* __restrict__ Wq, const float* __restrict__ Wk,
                               const float* __restrict__ Wv, fp16* __restrict__ w) {
    int idx = blockIdx.x * 256 + threadIdx.x;
    int k = idx / 3072, n = idx % 3072;
    int which = n >> 10, rem = n & 1023, hh = rem >> 6, d = rem & 63;
    const float* W = (which == 0) ? Wq : (which == 1) ? Wk : Wv;
    w[idx] = __float2half_rn(W[(size_t)hh * E_ * 64 + (size_t)k * 64 + d]);
}

__global__ void quant_w_kernel(const float* __restrict__ src, fp16* __restrict__ dst, int n) {
    int idx = blockIdx.x * 256 + threadIdx.x;
    if (idx < n) dst[idx] = __float2half_rn(src[idx]);
}

// ---------------- layernorm (emits fp16) ----------------
__device__ __forceinline__ float blockSum256(float v, float* sh) {
    __syncthreads();
    #pragma unroll
    for (int o = 16; o > 0; o >>= 1) v += __shfl_xor_sync(0xffffffffu, v, o);
    if ((threadIdx.x & 31) == 0) sh[threadIdx.x >> 5] = v;
    __syncthreads();
    if (threadIdx.x < 32) {
        float t = (threadIdx.x < 8) ? sh[threadIdx.x] : 0.0f;
        #pragma unroll
        for (int o = 4; o > 0; o >>= 1) t += __shfl_xor_sync(0xffffffffu, t, o);
        if (threadIdx.x == 0) sh[0] = t;
    }
    __syncthreads();
    return sh[0];
}

__global__ void ln_kernel(const float* __restrict__ x, const float* __restrict__ w,
                          const float* __restrict__ bb, fp16* __restrict__ out) {
    __shared__ float sh[8];
    size_t row = blockIdx.x;
    int tid = threadIdx.x;
    const float4 v = ((const float4*)(x + row * E_))[tid];
    float s = v.x + v.y + v.z + v.w;
    s = blockSum256(s, sh);
    float mu = s * (1.0f / E_);
    float dx = v.x - mu, dy = v.y - mu, dz = v.z - mu, dw = v.w - mu;
    float ss = dx * dx + dy * dy + dz * dz + dw * dw;
    ss = blockSum256(ss, sh);
    float inv = rsqrtf(ss * (1.0f / E_) + EPS);
    float4 w4 = ((const float4*)w)[tid];
    float4 b4 = ((const float4*)bb)[tid];
    float4 r;
    r.x = dx * inv * w4.x + b4.x;
    r.y = dy * inv * w4.y + b4.y;
    r.z = dz * inv * w4.z + b4.z;
    r.w = dw * inv * w4.w + b4.w;
    h2store4(r, out, row * E_ + tid * 4);
}

// ---------------- single-pass fp16 tensor-core GEMM ----------------
// CTA 128x128, K-stage 32. smem: A[128][40] (80B pitch), B[32][136] (272B pitch)
#define A_BYTES 10240
#define B_BYTES 8704
#define STAGE_BYTES (A_BYTES + B_BYTES)        // 18944
#define SM_TOTAL (2 * STAGE_BYTES)             // 37888

template <bool BIAS, bool RESID, bool RELU, bool HALFOUT>
__global__ __launch_bounds__(256, 2) void gemm_mma_kernel(
    const fp16* __restrict__ Aw, const fp16* __restrict__ Bw,
    const float* __restrict__ bias, const float* __restrict__ Rm,
    float* __restrict__ Cf, fp16* __restrict__ Ch,
    int N, int K) {
    extern __shared__ char sm[];
    const u32 smb = smem_u32(sm);

    int tid = threadIdx.x;
    int lane = tid & 31, wid = tid >> 5;
    int warpM = (wid >> 2) * 64, warpN = (wid & 3) * 32;
    int bm = blockIdx.y * 128, bn = blockIdx.x * 128;

    size_t a_src = (size_t)(bm + (tid >> 1)) * K + (tid & 1) * 16;
    size_t b_src = (size_t)(tid >> 3) * N + bn + (tid & 7) * 16;
    u32 a_dst = (tid >> 1) * 80 + (tid & 1) * 32;
    u32 b_dst = (tid >> 3) * 272 + (tid & 7) * 32;

    int a_row = warpM + (lane & 7) + ((lane >> 3) & 1) * 8;
    u32 a_off = a_row * 80 + (lane >> 4) * 16;
    u32 b_off = (lane & 15) * 272 + warpN * 2;

    float acc[4][4][4];
    #pragma unroll
    for (int i = 0; i < 4; i++)
        #pragma unroll
        for (int j = 0; j < 4; j++)
            #pragma unroll
            for (int c = 0; c < 4; c++) acc[i][j][c] = 0.0f;

    const int nk = K >> 5;

    // prologue: stage 0
    {
        u32 sb = smb;
        #pragma unroll
        for (int c = 0; c < 2; c++) {
            cp16(sb + a_dst + c * 16, Aw + a_src + c * 8);
            cp16(sb + A_BYTES + b_dst + c * 16, Bw + b_src + c * 8);
        }
        cp_commit();
    }

    for (int kt = 0; kt < nk; kt++) {
        cp_wait0();
        __syncthreads();
        u32 cur = smb + (kt & 1) * STAGE_BYTES;

        if (kt + 1 < nk) {
            u32 nb = smb + ((kt + 1) & 1) * STAGE_BYTES;
            size_t ak = a_src + (size_t)(kt + 1) * 32;
            size_t bk = b_src + (size_t)(kt + 1) * 32 * N;
            #pragma unroll
            for (int c = 0; c < 2; c++) {
                cp16(nb + a_dst + c * 16, Aw + ak + c * 8);
                cp16(nb + A_BYTES + b_dst + c * 16, Bw + bk + c * 8);
            }
            cp_commit();
        }

        #pragma unroll
        for (int ks = 0; ks < 2; ks++) {
            u32 bw[4][2];
            #pragma unroll
            for (int ni = 0; ni < 4; ni++) {
                u32 ba = cur + A_BYTES + b_off + ni * 16 + ks * 4352;
                ldsm2t(ba, bw[ni][0], bw[ni][1]);
            }
            #pragma unroll
            for (int mi = 0; mi < 4; mi++) {
                u32 ar[4];
                u32 aa = cur + a_off + mi * 1280 + ks * 32;
                ldsm4(aa, ar[0], ar[1], ar[2], ar[3]);
                #pragma unroll
                for (int ni = 0; ni < 4; ni++)
                    mma_fp16(acc[mi][ni], ar, bw[ni]);
            }
        }
    }

    // epilogue
    int g = lane >> 2, tg = lane & 3;
    #pragma unroll
    for (int mi = 0; mi < 4; mi++) {
        #pragma unroll
        for (int ni = 0; ni < 4; ni++) {
            int col = bn + warpN + ni * 8 + tg * 2;
            #pragma unroll
            for (int half = 0; half < 2; half++) {
                int row = bm + warpM + mi * 16 + g + half * 8;
                float vx = acc[mi][ni][half * 2 + 0];
                float vy = acc[mi][ni][half * 2 + 1];
                if (BIAS) {
                    float2 bb = *(const float2*)(bias + col);
                    vx += bb.x; vy += bb.y;
                }
                size_t off = (size_t)row * N + col;
                if (RESID) {
                    float2 rr = *(const float2*)(Rm + off);
                    vx += rr.x; vy += rr.y;
                }
                if (RELU) { vx = fmaxf(vx, 0.0f); vy = fmaxf(vy, 0.0f); }
                if (HALFOUT) {
                    __half2 hv = __floats2half2_rn(vx, vy);
                    *(__half2*)(Ch + off) = hv;
                } else {
                    float2 o; o.x = vx; o.y = vy;
                    *(float2*)(Cf + off) = o;
                }
            }
        }
    }
}

// ---------------- flash attention (fp32 SIMT, fp16 output) ----------------
#define APAD 68
__global__ __launch_bounds__(256) void attn_kernel(const float* __restrict__ qkv,
                                                   fp16* __restrict__ oh) {
    extern __shared__ float smf[];
    float* Qt  = smf;
    float* Kst = smf + 64 * APAD;
    float* Vs  = smf + 2 * 64 * APAD;
    float* St  = smf + 3 * 64 * APAD;

    int qt = blockIdx.x, h = blockIdx.y, b = blockIdx.z;
    int tid = threadIdx.x, tx = tid & 15, ty = tid >> 4;
    int t0 = qt * 64;
    size_t base = (size_t)b * T_ * 3072;

    #pragma unroll
    for (int l = 0; l < 4; l++) {
        int idx = l * 256 + tid;
        int r = idx >> 4, d4 = (idx & 15) * 4;
        float4 v = *(const float4*)(qkv + base + (size_t)(t0 + r) * 3072 + h * 64 + d4);
        Qt[(d4 + 0) * APAD + r] = v.x;
        Qt[(d4 + 1) * APAD + r] = v.y;
        Qt[(d4 + 2) * APAD + r] = v.z;
        Qt[(d4 + 3) * APAD + r] = v.w;
    }

    float o[4][4], m[4], l_[4];
    #pragma unroll
    for (int i = 0; i < 4; i++) {
        m[i] = -1e30f; l_[i] = 0.0f;
        #pragma unroll
        for (int j = 0; j < 4; j++) o[i][j] = 0.0f;
    }

    for (int ktile = 0; ktile <= qt; ++ktile) {
        __syncthreads();
        int k0 = ktile * 64;
        #pragma unroll
        for (int l = 0; l < 4; l++) {
            int idx = l * 256 + tid;
            int r = idx >> 4, d4 = (idx & 15) * 4;
            float4 kv = *(const float4*)(qkv + base + (size_t)(k0 + r) * 3072 + 1024 + h * 64 + d4);
            Kst[(d4 + 0) * APAD + r] = kv.x;
            Kst[(d4 + 1) * APAD + r] = kv.y;
            Kst[(d4 + 2) * APAD + r] = kv.z;
            Kst[(d4 + 3) * APAD + r] = kv.w;
            float4 vv = *(const float4*)(qkv + base + (size_t)(k0 + r) * 3072 + 2048 + h * 64 + d4);
            *(float4*)&Vs[r * APAD + d4] = vv;
        }
        __syncthreads();

        float s[4][4];
        #pragma unroll
        for (int i = 0; i < 4; i++)
            #pragma unroll
            for (int j = 0; j < 4; j++) s[i][j] = 0.0f;

        for (int d = 0; d < 64; d++) {
            float4 a = *(float4*)&Qt[d * APAD + ty * 4];
            float4 cc = *(float4*)&Kst[d * APAD + tx * 4];
            float av[4] = {a.x, a.y, a.z, a.w};
            float cv[4] = {cc.x, cc.y, cc.z, cc.w};
            #pragma unroll
            for (int i = 0; i < 4; i++)
                #pragma unroll
                for (int j = 0; j < 4; j++) s[i][j] += av[i] * cv[j];
        }
        #pragma unroll
        for (int i = 0; i < 4; i++)
            #pragma unroll
            for (int j = 0; j < 4; j++) s[i][j] *= SCALE;

        if (ktile == qt) {
            #pragma unroll
            for (int i = 0; i < 4; i++)
                #pragma unroll
                for (int j = 0; j < 4; j++)
                    if (k0 + tx * 4 + j > t0 + ty * 4 + i) s[i][j] = -1e30f;
        }

        #pragma unroll
        for (int i = 0; i < 4; i++) {
            float mx = fmaxf(fmaxf(s[i][0], s[i][1]), fmaxf(s[i][2], s[i][3]));
            #pragma unroll
            for (int off = 8; off > 0; off >>= 1)
                mx = fmaxf(mx, __shfl_xor_sync(0xffffffffu, mx, off, 16));
            float mn = fmaxf(m[i], mx);
            float al = __expf(m[i] - mn);
            float rs = 0.0f;
            #pragma unroll
            for (int j = 0; j < 4; j++) {
                float p = __expf(s[i][j] - mn);
                s[i][j] = p;
                rs += p;
            }
            #pragma unroll
            for (int off = 8; off > 0; off >>= 1)
                rs += __shfl_xor_sync(0xffffffffu, rs, off, 16);
            l_[i] = l_[i] * al + rs;
            m[i] = mn;
            #pragma unroll
            for (int j = 0; j < 4; j++) o[i][j] *= al;
            #pragma unroll
            for (int j = 0; j < 4; j++)
                St[(tx * 4 + j) * APAD + ty * 4 + i] = s[i][j];
        }
        __syncthreads();

        for (int kc = 0; kc < 64; kc++) {
            float4 a = *(float4*)&St[kc * APAD + ty * 4];
            float4 vv = *(float4*)&Vs[kc * APAD + tx * 4];
            float av[4] = {a.x, a.y, a.z, a.w};
            float bv[4] = {vv.x, vv.y, vv.z, vv.w};
            #pragma unroll
            for (int i = 0; i < 4; i++)
                #pragma unroll
                for (int j = 0; j < 4; j++) o[i][j] += av[i] * bv[j];
        }
    }

    #pragma unroll
    for (int i = 0; i < 4; i++) {
        float inv = 1.0f / l_[i];
        float4 v;
        v.x = o[i][0] * inv; v.y = o[i][1] * inv;
        v.z = o[i][2] * inv; v.w = o[i][3] * inv;
        h2store4(v, oh, ((size_t)b * T_ + t0 + ty * 4 + i) * E_ + h * 64 + tx * 4);
    }
}

// ---------------- launch ----------------
extern "C" void kernel_launch(void* const* d_in, const int* in_sizes, int n_in,
                              void* d_out, int out_size) {
    const float* x    = (const float*)d_in[0];
    const float* Wq   = (const float*)d_in[1];
    const float* Wk   = (const float*)d_in[2];
    const float* Wv   = (const float*)d_in[3];
    const float* Wo   = (const float*)d_in[4];
    const float* bo   = (const float*)d_in[5];
    const float* W1   = (const float*)d_in[6];
    const float* b1   = (const float*)d_in[7];
    const float* W2   = (const float*)d_in[8];
    const float* b2   = (const float*)d_in[9];
    const float* ln1w = (const float*)d_in[10];
    const float* ln1b = (const float*)d_in[11];
    const float* ln2w = (const float*)d_in[12];
    const float* ln2b = (const float*)d_in[13];
    float* out = (float*)d_out;

    fp16 *h, *w3, *wo, *w1, *w2, *attn, *u;
    float *qkv, *x2;
    cudaGetSymbolAddress((void**)&h, g_h);
    cudaGetSymbolAddress((void**)&w3, g_w3);
    cudaGetSymbolAddress((void**)&wo, g_wo);
    cudaGetSymbolAddress((void**)&w1, g_w1);
    cudaGetSymbolAddress((void**)&w2, g_w2);
    cudaGetSymbolAddress((void**)&qkv, g_qkv);
    cudaGetSymbolAddress((void**)&attn, g_attn);
    cudaGetSymbolAddress((void**)&x2, g_x2);
    cudaGetSymbolAddress((void**)&u, g_u);

    cudaFuncSetAttribute(attn_kernel, cudaFuncAttributeMaxDynamicSharedMemorySize,
                         4 * 64 * APAD * 4);
    cudaFuncSetAttribute(gemm_mma_kernel<false, false, false, false>,
                         cudaFuncAttributeMaxDynamicSharedMemorySize, SM_TOTAL);
    cudaFuncSetAttribute(gemm_mma_kernel<true, true, false, false>,
                         cudaFuncAttributeMaxDynamicSharedMemorySize, SM_TOTAL);
    cudaFuncSetAttribute(gemm_mma_kernel<true, false, true, true>,
                         cudaFuncAttributeMaxDynamicSharedMemorySize, SM_TOTAL);

    // weight prep (fp16 quantize, [K][N] layouts)
    pack_w3_kernel<<<(3 * E_ * E_) / 256, 256>>>(Wq, Wk, Wv, w3);
    quant_w_kernel<<<(E_ * E_) / 256, 256>>>(Wo, wo, E_ * E_);
    quant_w_kernel<<<(E_ * P_) / 256, 256>>>(W1, w1, E_ * P_);
    quant_w_kernel<<<(P_ * E_) / 256, 256>>>(W2, w2, P_ * E_);

    // LN1
    ln_kernel<<<M_, 256>>>(x, ln1w, ln1b, h);

    // QKV: [M,1024] @ [1024,3072] -> fp32
    gemm_mma_kernel<false, false, false, false><<<dim3(3072 / 128, M_ / 128), 256, SM_TOTAL>>>(
        h, w3, nullptr, nullptr, qkv, nullptr, 3072, E_);

    // attention
    attn_kernel<<<dim3(T_ / 64, H_, B_), 256, 4 * 64 * APAD * 4>>>(qkv, attn);

    // out-proj + bias + residual(x) -> fp32 x2
    gemm_mma_kernel<true, true, false, false><<<dim3(E_ / 128, M_ / 128), 256, SM_TOTAL>>>(
        attn, wo, bo, x, x2, nullptr, E_, E_);

    // LN2
    ln_kernel<<<M_, 256>>>(x2, ln2w, ln2b, h);

    // FFN1: relu(h @ W1 + b1) -> fp16 u
    gemm_mma_kernel<true, false, true, true><<<dim3(P_ / 128, M_ / 128), 256, SM_TOTAL>>>(
        h, w1, b1, nullptr, nullptr, u, P_, E_);

    // FFN2: x2 + u @ W2 + b2 -> out fp32
    gemm_mma_kernel<true, true, false, false><<<dim3(E_ / 128, M_ / 128), 256, SM_TOTAL>>>(
        u, w2, b2, x2, out, nullptr, E_, P_);
}

// round 8
// speedup vs baseline: 6.4360x; 1.2081x over previous
#include <cuda_runtime.h>
#include <cuda_fp16.h>
#include <cstdint>

#define B_  64
#define T_  320
#define E_  1024
#define H_  16
#define P_  4096
#define M_  (B_ * T_)          // 20480 tokens
#define EPS 1e-5f
#define SCALE 0.03125f          // E^-0.5

typedef unsigned u32;
typedef __half fp16;

// ---------------- scratch (device globals) ----------------
__device__ fp16 g_h[(size_t)M_ * E_];
__device__ fp16 g_w3[(size_t)E_ * 3 * E_];      // [K=1024][N=3072]
__device__ fp16 g_wo[(size_t)E_ * E_];          // [K][N]
__device__ fp16 g_w1[(size_t)E_ * P_];          // [K=1024][N=4096]
__device__ fp16 g_w2[(size_t)P_ * E_];          // [K=4096][N=1024]
__device__ fp16 g_qkv[(size_t)M_ * 3 * E_];     // fp16 q|k|v
__device__ fp16 g_attn[(size_t)M_ * E_];
__device__ float g_x2[(size_t)M_ * E_];
__device__ fp16 g_u[(size_t)M_ * P_];

// ---------------- helpers ----------------
__device__ __forceinline__ u32 smem_u32(const void* p) {
    return (u32)__cvta_generic_to_shared(p);
}
__device__ __forceinline__ u32 pack_h2(float a, float b) {
    union { __half2 h; u32 u; } c;
    c.h = __floats2half2_rn(a, b);
    return c.u;
}
__device__ __forceinline__ void cp16(u32 dst, const void* src) {
    asm volatile("cp.async.cg.shared.global [%0], [%1], 16;" :: "r"(dst), "l"(src));
}
__device__ __forceinline__ void cp_commit() { asm volatile("cp.async.commit_group;"); }
__device__ __forceinline__ void cp_wait0() { asm volatile("cp.async.wait_group 0;"); }

__device__ __forceinline__ void ldsm4(u32 addr, u32& r0, u32& r1, u32& r2, u32& r3) {
    asm volatile("ldmatrix.sync.aligned.m8n8.x4.shared.b16 {%0,%1,%2,%3}, [%4];"
                 : "=r"(r0), "=r"(r1), "=r"(r2), "=r"(r3) : "r"(addr));
}
__device__ __forceinline__ void ldsm2t(u32 addr, u32& r0, u32& r1) {
    asm volatile("ldmatrix.sync.aligned.m8n8.x2.trans.shared.b16 {%0,%1}, [%2];"
                 : "=r"(r0), "=r"(r1) : "r"(addr));
}
__device__ __forceinline__ void mma_fp16(float* c, const u32* a, const u32* b) {
    asm volatile("mma.sync.aligned.m16n8k16.row.col.f32.f16.f16.f32 "
                 "{%0,%1,%2,%3}, {%4,%5,%6,%7}, {%8,%9}, {%0,%1,%2,%3};"
                 : "+f"(c[0]), "+f"(c[1]), "+f"(c[2]), "+f"(c[3])
                 : "r"(a[0]), "r"(a[1]), "r"(a[2]), "r"(a[3]), "r"(b[0]), "r"(b[1]));
}
__device__ __forceinline__ void h2store4(float4 v, fp16* dst, size_t idx) {
    uint2 u;
    u.x = pack_h2(v.x, v.y);
    u.y = pack_h2(v.z, v.w);
    *(uint2*)(dst + idx) = u;
}

// ---------------- weight prep ----------------
__global__ void pack_w3_kernel(const float* __restrict__ Wq, const float* __restrict__ Wk,
                               const float* __restrict__ Wv, fp16* __restrict__ w) {
    int idx = blockIdx.x * 256 + threadIdx.x;
    int k = idx / 3072, n = idx % 3072;
    int which = n >> 10, rem = n & 1023, hh = rem >> 6, d = rem & 63;
    const float* W = (which == 0) ? Wq : (which == 1) ? Wk : Wv;
    w[idx] = __float2half_rn(W[(size_t)hh * E_ * 64 + (size_t)k * 64 + d]);
}

__global__ void quant_w_kernel(const float* __restrict__ src, fp16* __restrict__ dst, int n) {
    int idx = blockIdx.x * 256 + threadIdx.x;
    if (idx < n) dst[idx] = __float2half_rn(src[idx]);
}

// ---------------- layernorm (emits fp16) ----------------
__device__ __forceinline__ float blockSum256(float v, float* sh) {
    __syncthreads();
    #pragma unroll
    for (int o = 16; o > 0; o >>= 1) v += __shfl_xor_sync(0xffffffffu, v, o);
    if ((threadIdx.x & 31) == 0) sh[threadIdx.x >> 5] = v;
    __syncthreads();
    if (threadIdx.x < 32) {
        float t = (threadIdx.x < 8) ? sh[threadIdx.x] : 0.0f;
        #pragma unroll
        for (int o = 4; o > 0; o >>= 1) t += __shfl_xor_sync(0xffffffffu, t, o);
        if (threadIdx.x == 0) sh[0] = t;
    }
    __syncthreads();
    return sh[0];
}

__global__ void ln_kernel(const float* __restrict__ x, const float* __restrict__ w,
                          const float* __restrict__ bb, fp16* __restrict__ out) {
    __shared__ float sh[8];
    size_t row = blockIdx.x;
    int tid = threadIdx.x;
    const float4 v = ((const float4*)(x + row * E_))[tid];
    float s = v.x + v.y + v.z + v.w;
    s = blockSum256(s, sh);
    float mu = s * (1.0f / E_);
    float dx = v.x - mu, dy = v.y - mu, dz = v.z - mu, dw = v.w - mu;
    float ss = dx * dx + dy * dy + dz * dz + dw * dw;
    ss = blockSum256(ss, sh);
    float inv = rsqrtf(ss * (1.0f / E_) + EPS);
    float4 w4 = ((const float4*)w)[tid];
    float4 b4 = ((const float4*)bb)[tid];
    float4 r;
    r.x = dx * inv * w4.x + b4.x;
    r.y = dy * inv * w4.y + b4.y;
    r.z = dz * inv * w4.z + b4.z;
    r.w = dw * inv * w4.w + b4.w;
    h2store4(r, out, row * E_ + tid * 4);
}

// ---------------- single-pass fp16 tensor-core GEMM ----------------
#define A_BYTES 10240
#define B_BYTES 8704
#define STAGE_BYTES (A_BYTES + B_BYTES)
#define SM_TOTAL (2 * STAGE_BYTES)

template <bool BIAS, bool RESID, bool RELU, bool HALFOUT>
__global__ __launch_bounds__(256, 2) void gemm_mma_kernel(
    const fp16* __restrict__ Aw, const fp16* __restrict__ Bw,
    const float* __restrict__ bias, const float* __restrict__ Rm,
    float* __restrict__ Cf, fp16* __restrict__ Ch,
    int N, int K) {
    extern __shared__ char sm[];
    const u32 smb = smem_u32(sm);

    int tid = threadIdx.x;
    int lane = tid & 31, wid = tid >> 5;
    int warpM = (wid >> 2) * 64, warpN = (wid & 3) * 32;
    int bm = blockIdx.y * 128, bn = blockIdx.x * 128;

    size_t a_src = (size_t)(bm + (tid >> 1)) * K + (tid & 1) * 16;
    size_t b_src = (size_t)(tid >> 3) * N + bn + (tid & 7) * 16;
    u32 a_dst = (tid >> 1) * 80 + (tid & 1) * 32;
    u32 b_dst = (tid >> 3) * 272 + (tid & 7) * 32;

    int a_row = warpM + (lane & 7) + ((lane >> 3) & 1) * 8;
    u32 a_off = a_row * 80 + (lane >> 4) * 16;
    u32 b_off = (lane & 15) * 272 + warpN * 2;

    float acc[4][4][4];
    #pragma unroll
    for (int i = 0; i < 4; i++)
        #pragma unroll
        for (int j = 0; j < 4; j++)
            #pragma unroll
            for (int c = 0; c < 4; c++) acc[i][j][c] = 0.0f;

    const int nk = K >> 5;
    {
        u32 sb = smb;
        #pragma unroll
        for (int c = 0; c < 2; c++) {
            cp16(sb + a_dst + c * 16, Aw + a_src + c * 8);
            cp16(sb + A_BYTES + b_dst + c * 16, Bw + b_src + c * 8);
        }
        cp_commit();
    }

    for (int kt = 0; kt < nk; kt++) {
        cp_wait0();
        __syncthreads();
        u32 cur = smb + (kt & 1) * STAGE_BYTES;

        if (kt + 1 < nk) {
            u32 nb = smb + ((kt + 1) & 1) * STAGE_BYTES;
            size_t ak = a_src + (size_t)(kt + 1) * 32;
            size_t bk = b_src + (size_t)(kt + 1) * 32 * N;
            #pragma unroll
            for (int c = 0; c < 2; c++) {
                cp16(nb + a_dst + c * 16, Aw + ak + c * 8);
                cp16(nb + A_BYTES + b_dst + c * 16, Bw + bk + c * 8);
            }
            cp_commit();
        }

        #pragma unroll
        for (int ks = 0; ks < 2; ks++) {
            u32 bw[4][2];
            #pragma unroll
            for (int ni = 0; ni < 4; ni++) {
                u32 ba = cur + A_BYTES + b_off + ni * 16 + ks * 4352;
                ldsm2t(ba, bw[ni][0], bw[ni][1]);
            }
            #pragma unroll
            for (int mi = 0; mi < 4; mi++) {
                u32 ar[4];
                u32 aa = cur + a_off + mi * 1280 + ks * 32;
                ldsm4(aa, ar[0], ar[1], ar[2], ar[3]);
                #pragma unroll
                for (int ni = 0; ni < 4; ni++)
                    mma_fp16(acc[mi][ni], ar, bw[ni]);
            }
        }
    }

    int g = lane >> 2, tg = lane & 3;
    #pragma unroll
    for (int mi = 0; mi < 4; mi++) {
        #pragma unroll
        for (int ni = 0; ni < 4; ni++) {
            int col = bn + warpN + ni * 8 + tg * 2;
            #pragma unroll
            for (int half = 0; half < 2; half++) {
                int row = bm + warpM + mi * 16 + g + half * 8;
                float vx = acc[mi][ni][half * 2 + 0];
                float vy = acc[mi][ni][half * 2 + 1];
                if (BIAS) {
                    float2 bb = *(const float2*)(bias + col);
                    vx += bb.x; vy += bb.y;
                }
                size_t off = (size_t)row * N + col;
                if (RESID) {
                    float2 rr = *(const float2*)(Rm + off);
                    vx += rr.x; vy += rr.y;
                }
                if (RELU) { vx = fmaxf(vx, 0.0f); vy = fmaxf(vy, 0.0f); }
                if (HALFOUT) {
                    u32 hv = pack_h2(vx, vy);
                    *(u32*)(Ch + off) = hv;
                } else {
                    float2 o; o.x = vx; o.y = vy;
                    *(float2*)(Cf + off) = o;
                }
            }
        }
    }
}

// ---------------- tensor-core flash attention ----------------
// Block: 128 threads = 4 warps, each warp owns 16 query rows. Tile: 64 q x 64 k.
// smem pitch 72 halves (144 B) -> conflict-free ldmatrix.
#define ATP 72
__global__ __launch_bounds__(128) void attn_mma_kernel(const fp16* __restrict__ qkv,
                                                       fp16* __restrict__ oh) {
    __shared__ fp16 sQ[64 * ATP];
    __shared__ fp16 sKt[64 * ATP];   // transposed: sKt[d][kc]
    __shared__ fp16 sV[64 * ATP];    // sV[kc][d]

    int qt = blockIdx.x, h = blockIdx.y, b = blockIdx.z;
    int tid = threadIdx.x, lane = tid & 31, w = tid >> 5;
    int g = lane >> 2, tg = lane & 3;
    int t0 = qt * 64;
    size_t base = (size_t)b * T_ * 3072;

    const u32 sQa = smem_u32(sQ);
    const u32 sKa = smem_u32(sKt);
    const u32 sVa = smem_u32(sV);

    // load Q tile (64 rows x 64 halves), direct copy
    #pragma unroll
    for (int i = 0; i < 4; i++) {
        int idx = i * 128 + tid;          // 512 chunks of 8 halves
        int r = idx >> 3, c8 = (idx & 7) * 8;
        uint4 v = *(const uint4*)(qkv + base + (size_t)(t0 + r) * 3072 + h * 64 + c8);
        *(uint4*)(sQ + r * ATP + c8) = v;
    }

    float o[8][4];
    #pragma unroll
    for (int j = 0; j < 8; j++)
        #pragma unroll
        for (int c = 0; c < 4; c++) o[j][c] = 0.0f;
    float mrow[2] = {-1e30f, -1e30f};
    float lrow[2] = {0.0f, 0.0f};

    int kv_r = tid >> 1, kv_dh = (tid & 1) * 32;   // K transpose mapping

    for (int ktile = 0; ktile <= qt; ++ktile) {
        __syncthreads();
        int k0 = ktile * 64;
        // K: load row kc=kv_r, halves kv_dh..kv_dh+31; store transposed
        {
            const fp16* kp = qkv + base + (size_t)(k0 + kv_r) * 3072 + 1024 + h * 64 + kv_dh;
            #pragma unroll
            for (int c = 0; c < 4; c++) {
                uint4 v = *(const uint4*)(kp + c * 8);
                fp16 hs[8];
                *(uint4*)hs = v;
                #pragma unroll
                for (int e = 0; e < 8; e++)
                    sKt[(kv_dh + c * 8 + e) * ATP + kv_r] = hs[e];
            }
        }
        // V: direct copy
        #pragma unroll
        for (int i = 0; i < 4; i++) {
            int idx = i * 128 + tid;
            int r = idx >> 3, c8 = (idx & 7) * 8;
            uint4 v = *(const uint4*)(qkv + base + (size_t)(k0 + r) * 3072 + 2048 + h * 64 + c8);
            *(uint4*)(sV + r * ATP + c8) = v;
        }
        __syncthreads();

        // S = Q(16x64) @ Kt  -> 8 n-tiles of 8 cols
        float cs[8][4];
        #pragma unroll
        for (int j = 0; j < 8; j++)
            #pragma unroll
            for (int c = 0; c < 4; c++) cs[j][c] = 0.0f;

        #pragma unroll
        for (int ks = 0; ks < 4; ks++) {
            u32 ar[4];
            u32 aa = sQa + (w * 16 + (lane & 7) + ((lane >> 3) & 1) * 8) * 144
                   + (lane >> 4) * 16 + ks * 32;
            ldsm4(aa, ar[0], ar[1], ar[2], ar[3]);
            #pragma unroll
            for (int j = 0; j < 8; j++) {
                u32 bw[2];
                ldsm2t(sKa + (ks * 16 + (lane & 15)) * 144 + j * 16, bw[0], bw[1]);
                mma_fp16(cs[j], ar, bw);
            }
        }

        // scale + causal mask
        #pragma unroll
        for (int j = 0; j < 8; j++)
            #pragma unroll
            for (int c = 0; c < 4; c++) cs[j][c] *= SCALE;
        if (ktile == qt) {
            int r0 = w * 16 + g, r1 = r0 + 8;
            #pragma unroll
            for (int j = 0; j < 8; j++) {
                int c0 = 8 * j + 2 * tg;
                if (c0 > r0) cs[j][0] = -1e30f;
                if (c0 + 1 > r0) cs[j][1] = -1e30f;
                if (c0 > r1) cs[j][2] = -1e30f;
                if (c0 + 1 > r1) cs[j][3] = -1e30f;
            }
        }

        // online softmax (2 rows per thread: g and g+8)
        float al[2];
        #pragma unroll
        for (int hr = 0; hr < 2; hr++) {
            float mx = -1e30f;
            #pragma unroll
            for (int j = 0; j < 8; j++)
                mx = fmaxf(mx, fmaxf(cs[j][hr * 2], cs[j][hr * 2 + 1]));
            mx = fmaxf(mx, __shfl_xor_sync(0xffffffffu, mx, 1));
            mx = fmaxf(mx, __shfl_xor_sync(0xffffffffu, mx, 2));
            float mn = fmaxf(mrow[hr], mx);
            al[hr] = __expf(mrow[hr] - mn);
            float rs = 0.0f;
            #pragma unroll
            for (int j = 0; j < 8; j++) {
                float p0 = __expf(cs[j][hr * 2] - mn);
                float p1 = __expf(cs[j][hr * 2 + 1] - mn);
                cs[j][hr * 2] = p0;
                cs[j][hr * 2 + 1] = p1;
                rs += p0 + p1;
            }
            rs += __shfl_xor_sync(0xffffffffu, rs, 1);
            rs += __shfl_xor_sync(0xffffffffu, rs, 2);
            lrow[hr] = lrow[hr] * al[hr] + rs;
            mrow[hr] = mn;
        }
        #pragma unroll
        for (int j = 0; j < 8; j++) {
            o[j][0] *= al[0]; o[j][1] *= al[0];
            o[j][2] *= al[1]; o[j][3] *= al[1];
        }

        // P fragments: C-frag -> A-frag repack (no smem)
        u32 aP[4][4];
        #pragma unroll
        for (int st = 0; st < 4; st++) {
            aP[st][0] = pack_h2(cs[2 * st][0], cs[2 * st][1]);
            aP[st][1] = pack_h2(cs[2 * st][2], cs[2 * st][3]);
            aP[st][2] = pack_h2(cs[2 * st + 1][0], cs[2 * st + 1][1]);
            aP[st][3] = pack_h2(cs[2 * st + 1][2], cs[2 * st + 1][3]);
        }

        // O += P(16x64) @ V(64x64)
        #pragma unroll
        for (int st = 0; st < 4; st++) {
            #pragma unroll
            for (int j2 = 0; j2 < 8; j2++) {
                u32 bw[2];
                ldsm2t(sVa + (st * 16 + (lane & 15)) * 144 + j2 * 16, bw[0], bw[1]);
                mma_fp16(o[j2], aP[st], bw);
            }
        }
    }

    // write out: O / l
    float inv0 = 1.0f / lrow[0], inv1 = 1.0f / lrow[1];
    int r0 = t0 + w * 16 + g;
    size_t ob = ((size_t)b * T_ + r0) * E_ + h * 64;
    #pragma unroll
    for (int j = 0; j < 8; j++) {
        int col = 8 * j + 2 * tg;
        *(u32*)(oh + ob + col) = pack_h2(o[j][0] * inv0, o[j][1] * inv0);
        *(u32*)(oh + ob + 8 * E_ + col) = pack_h2(o[j][2] * inv1, o[j][3] * inv1);
    }
}

// ---------------- launch ----------------
extern "C" void kernel_launch(void* const* d_in, const int* in_sizes, int n_in,
                              void* d_out, int out_size) {
    const float* x    = (const float*)d_in[0];
    const float* Wq   = (const float*)d_in[1];
    const float* Wk   = (const float*)d_in[2];
    const float* Wv   = (const float*)d_in[3];
    const float* Wo   = (const float*)d_in[4];
    const float* bo   = (const float*)d_in[5];
    const float* W1   = (const float*)d_in[6];
    const float* b1   = (const float*)d_in[7];
    const float* W2   = (const float*)d_in[8];
    const float* b2   = (const float*)d_in[9];
    const float* ln1w = (const float*)d_in[10];
    const float* ln1b = (const float*)d_in[11];
    const float* ln2w = (const float*)d_in[12];
    const float* ln2b = (const float*)d_in[13];
    float* out = (float*)d_out;

    fp16 *h, *w3, *wo, *w1, *w2, *qkv, *attn, *u;
    float *x2;
    cudaGetSymbolAddress((void**)&h, g_h);
    cudaGetSymbolAddress((void**)&w3, g_w3);
    cudaGetSymbolAddress((void**)&wo, g_wo);
    cudaGetSymbolAddress((void**)&w1, g_w1);
    cudaGetSymbolAddress((void**)&w2, g_w2);
    cudaGetSymbolAddress((void**)&qkv, g_qkv);
    cudaGetSymbolAddress((void**)&attn, g_attn);
    cudaGetSymbolAddress((void**)&x2, g_x2);
    cudaGetSymbolAddress((void**)&u, g_u);

    cudaFuncSetAttribute(gemm_mma_kernel<false, false, false, true>,
                         cudaFuncAttributeMaxDynamicSharedMemorySize, SM_TOTAL);
    cudaFuncSetAttribute(gemm_mma_kernel<true, true, false, false>,
                         cudaFuncAttributeMaxDynamicSharedMemorySize, SM_TOTAL);
    cudaFuncSetAttribute(gemm_mma_kernel<true, false, true, true>,
                         cudaFuncAttributeMaxDynamicSharedMemorySize, SM_TOTAL);

    // weight prep
    pack_w3_kernel<<<(3 * E_ * E_) / 256, 256>>>(Wq, Wk, Wv, w3);
    quant_w_kernel<<<(E_ * E_) / 256, 256>>>(Wo, wo, E_ * E_);
    quant_w_kernel<<<(E_ * P_) / 256, 256>>>(W1, w1, E_ * P_);
    quant_w_kernel<<<(P_ * E_) / 256, 256>>>(W2, w2, P_ * E_);

    // LN1
    ln_kernel<<<M_, 256>>>(x, ln1w, ln1b, h);

    // QKV -> fp16
    gemm_mma_kernel<false, false, false, true><<<dim3(3072 / 128, M_ / 128), 256, SM_TOTAL>>>(
        h, w3, nullptr, nullptr, nullptr, qkv, 3072, E_);

    // attention (tensor cores)
    attn_mma_kernel<<<dim3(T_ / 64, H_, B_), 128>>>(qkv, attn);

    // out-proj + bias + residual(x) -> fp32 x2
    gemm_mma_kernel<true, true, false, false><<<dim3(E_ / 128, M_ / 128), 256, SM_TOTAL>>>(
        attn, wo, bo, x, x2, nullptr, E_, E_);

    // LN2
    ln_kernel<<<M_, 256>>>(x2, ln2w, ln2b, h);

    // FFN1: relu -> fp16 u
    gemm_mma_kernel<true, false, true, true><<<dim3(P_ / 128, M_ / 128), 256, SM_TOTAL>>>(
        h, w1, b1, nullptr, nullptr, u, P_, E_);

    // FFN2 -> out fp32
    gemm_mma_kernel<true, true, false, false><<<dim3(E_ / 128, M_ / 128), 256, SM_TOTAL>>>(
        u, w2, b2, x2, out, nullptr, E_, P_);
}

// round 9
// speedup vs baseline: 7.9738x; 1.2389x over previous
#include <cuda_runtime.h>
#include <cuda_fp16.h>
#include <cstdint>

#define B_  64
#define T_  320
#define E_  1024
#define H_  16
#define P_  4096
#define M_  (B_ * T_)          // 20480 tokens
#define EPS 1e-5f
#define SCALE 0.03125f          // E^-0.5

typedef unsigned u32;
typedef __half fp16;

// ---------------- scratch (device globals) ----------------
__device__ fp16 g_h[(size_t)M_ * E_];
__device__ fp16 g_w3[(size_t)E_ * 3 * E_];      // [K=1024][N=3072]
__device__ fp16 g_wo[(size_t)E_ * E_];          // [K][N]
__device__ fp16 g_w1[(size_t)E_ * P_];          // [K=1024][N=4096]
__device__ fp16 g_w2[(size_t)P_ * E_];          // [K=4096][N=1024]
__device__ fp16 g_qkv[(size_t)M_ * 3 * E_];     // fp16 q|k|v
__device__ fp16 g_attn[(size_t)M_ * E_];
__device__ float g_x2[(size_t)M_ * E_];
__device__ fp16 g_u[(size_t)M_ * P_];

// ---------------- helpers ----------------
__device__ __forceinline__ u32 smem_u32(const void* p) {
    return (u32)__cvta_generic_to_shared(p);
}
__device__ __forceinline__ u32 pack_h2(float a, float b) {
    union { __half2 h; u32 u; } c;
    c.h = __floats2half2_rn(a, b);
    return c.u;
}
__device__ __forceinline__ void cp16(u32 dst, const void* src) {
    asm volatile("cp.async.cg.shared.global [%0], [%1], 16;" :: "r"(dst), "l"(src));
}
__device__ __forceinline__ void cp_commit() { asm volatile("cp.async.commit_group;"); }
__device__ __forceinline__ void cp_wait0() { asm volatile("cp.async.wait_group 0;"); }

__device__ __forceinline__ void ldsm4(u32 addr, u32& r0, u32& r1, u32& r2, u32& r3) {
    asm volatile("ldmatrix.sync.aligned.m8n8.x4.shared.b16 {%0,%1,%2,%3}, [%4];"
                 : "=r"(r0), "=r"(r1), "=r"(r2), "=r"(r3) : "r"(addr));
}
__device__ __forceinline__ void ldsm4t(u32 addr, u32& r0, u32& r1, u32& r2, u32& r3) {
    asm volatile("ldmatrix.sync.aligned.m8n8.x4.trans.shared.b16 {%0,%1,%2,%3}, [%4];"
                 : "=r"(r0), "=r"(r1), "=r"(r2), "=r"(r3) : "r"(addr));
}
__device__ __forceinline__ void ldsm2t(u32 addr, u32& r0, u32& r1) {
    asm volatile("ldmatrix.sync.aligned.m8n8.x2.trans.shared.b16 {%0,%1}, [%2];"
                 : "=r"(r0), "=r"(r1) : "r"(addr));
}
__device__ __forceinline__ void mma_fp16(float* c, const u32* a, const u32* b) {
    asm volatile("mma.sync.aligned.m16n8k16.row.col.f32.f16.f16.f32 "
                 "{%0,%1,%2,%3}, {%4,%5,%6,%7}, {%8,%9}, {%0,%1,%2,%3};"
                 : "+f"(c[0]), "+f"(c[1]), "+f"(c[2]), "+f"(c[3])
                 : "r"(a[0]), "r"(a[1]), "r"(a[2]), "r"(a[3]), "r"(b[0]), "r"(b[1]));
}
__device__ __forceinline__ void h2store4(float4 v, fp16* dst, size_t idx) {
    uint2 u;
    u.x = pack_h2(v.x, v.y);
    u.y = pack_h2(v.z, v.w);
    *(uint2*)(dst + idx) = u;
}

// ---------------- weight prep ----------------
__global__ void pack_w3_kernel(const float* __restrict__ Wq, const float* __restrict__ Wk,
                               const float* __restrict__ Wv, fp16* __restrict__ w) {
    int idx = blockIdx.x * 256 + threadIdx.x;
    int k = idx / 3072, n = idx % 3072;
    int which = n >> 10, rem = n & 1023, hh = rem >> 6, d = rem & 63;
    const float* W = (which == 0) ? Wq : (which == 1) ? Wk : Wv;
    w[idx] = __float2half_rn(W[(size_t)hh * E_ * 64 + (size_t)k * 64 + d]);
}

__global__ void quant_w_kernel(const float* __restrict__ src, fp16* __restrict__ dst, int n) {
    int idx = blockIdx.x * 256 + threadIdx.x;
    if (idx < n) dst[idx] = __float2half_rn(src[idx]);
}

// ---------------- layernorm (emits fp16) ----------------
__device__ __forceinline__ float blockSum256(float v, float* sh) {
    __syncthreads();
    #pragma unroll
    for (int o = 16; o > 0; o >>= 1) v += __shfl_xor_sync(0xffffffffu, v, o);
    if ((threadIdx.x & 31) == 0) sh[threadIdx.x >> 5] = v;
    __syncthreads();
    if (threadIdx.x < 32) {
        float t = (threadIdx.x < 8) ? sh[threadIdx.x] : 0.0f;
        #pragma unroll
        for (int o = 4; o > 0; o >>= 1) t += __shfl_xor_sync(0xffffffffu, t, o);
        if (threadIdx.x == 0) sh[0] = t;
    }
    __syncthreads();
    return sh[0];
}

__global__ void ln_kernel(const float* __restrict__ x, const float* __restrict__ w,
                          const float* __restrict__ bb, fp16* __restrict__ out) {
    __shared__ float sh[8];
    size_t row = blockIdx.x;
    int tid = threadIdx.x;
    const float4 v = ((const float4*)(x + row * E_))[tid];
    float s = v.x + v.y + v.z + v.w;
    s = blockSum256(s, sh);
    float mu = s * (1.0f / E_);
    float dx = v.x - mu, dy = v.y - mu, dz = v.z - mu, dw = v.w - mu;
    float ss = dx * dx + dy * dy + dz * dz + dw * dw;
    ss = blockSum256(ss, sh);
    float inv = rsqrtf(ss * (1.0f / E_) + EPS);
    float4 w4 = ((const float4*)w)[tid];
    float4 b4 = ((const float4*)bb)[tid];
    float4 r;
    r.x = dx * inv * w4.x + b4.x;
    r.y = dy * inv * w4.y + b4.y;
    r.z = dz * inv * w4.z + b4.z;
    r.w = dw * inv * w4.w + b4.w;
    h2store4(r, out, row * E_ + tid * 4);
}

// ---------------- single-pass fp16 tensor-core GEMM ----------------
// CTA 128x128, 4 warps (2x2), warp tile 64x64. K-stage 32.
// smem: A[128][40] (80B pitch), B[32][136] (272B pitch)
#define A_BYTES 10240
#define B_BYTES 8704
#define STAGE_BYTES (A_BYTES + B_BYTES)
#define SM_TOTAL (2 * STAGE_BYTES)

template <bool BIAS, bool RESID, bool RELU, bool HALFOUT>
__global__ __launch_bounds__(128, 2) void gemm_mma_kernel(
    const fp16* __restrict__ Aw, const fp16* __restrict__ Bw,
    const float* __restrict__ bias, const float* __restrict__ Rm,
    float* __restrict__ Cf, fp16* __restrict__ Ch,
    int N, int K) {
    extern __shared__ char sm[];
    const u32 smb = smem_u32(sm);

    int tid = threadIdx.x;
    int lane = tid & 31, wid = tid >> 5;
    int warpM = (wid >> 1) * 64, warpN = (wid & 1) * 64;
    int bm = blockIdx.y * 128, bn = blockIdx.x * 128;

    // copy indexing (128 threads, 4 chunks of 16B per array per thread)
    int a_cr = tid >> 2, a_cc = tid & 3;        // +c*32 rows
    int b_cr = tid >> 4, b_cc = tid & 15;       // +c*8 rows
    u32 a_dst0 = a_cr * 80 + a_cc * 16;
    u32 b_dst0 = b_cr * 272 + b_cc * 16;

    // ldmatrix addresses
    u32 a_off = (warpM + (lane & 15)) * 80 + (lane >> 4) * 16;
    u32 b_off = (lane & 15) * 272 + warpN * 2 + (lane >> 4) * 16;

    float acc[4][8][4];
    #pragma unroll
    for (int i = 0; i < 4; i++)
        #pragma unroll
        for (int j = 0; j < 8; j++)
            #pragma unroll
            for (int c = 0; c < 4; c++) acc[i][j][c] = 0.0f;

    const int nk = K >> 5;

    // prologue: stage 0
    {
        u32 sb = smb;
        #pragma unroll
        for (int c = 0; c < 4; c++) {
            cp16(sb + a_dst0 + c * 32 * 80,
                 Aw + (size_t)(bm + a_cr + c * 32) * K + a_cc * 8);
            cp16(sb + A_BYTES + b_dst0 + c * 8 * 272,
                 Bw + (size_t)(b_cr + c * 8) * N + bn + b_cc * 8);
        }
        cp_commit();
    }

    for (int kt = 0; kt < nk; kt++) {
        cp_wait0();
        __syncthreads();
        u32 cur = smb + (kt & 1) * STAGE_BYTES;

        if (kt + 1 < nk) {
            u32 nb = smb + ((kt + 1) & 1) * STAGE_BYTES;
            int k0 = (kt + 1) * 32;
            #pragma unroll
            for (int c = 0; c < 4; c++) {
                cp16(nb + a_dst0 + c * 32 * 80,
                     Aw + (size_t)(bm + a_cr + c * 32) * K + k0 + a_cc * 8);
                cp16(nb + A_BYTES + b_dst0 + c * 8 * 272,
                     Bw + (size_t)(k0 + b_cr + c * 8) * N + bn + b_cc * 8);
            }
            cp_commit();
        }

        #pragma unroll
        for (int ks = 0; ks < 2; ks++) {
            u32 bw[8][2];
            #pragma unroll
            for (int nj = 0; nj < 4; nj++) {
                u32 ba = cur + A_BYTES + b_off + nj * 32 + ks * 4352;
                ldsm4t(ba, bw[2 * nj][0], bw[2 * nj][1], bw[2 * nj + 1][0], bw[2 * nj + 1][1]);
            }
            #pragma unroll
            for (int mi = 0; mi < 4; mi++) {
                u32 ar[4];
                u32 aa = cur + a_off + mi * 1280 + ks * 32;
                ldsm4(aa, ar[0], ar[1], ar[2], ar[3]);
                #pragma unroll
                for (int ni = 0; ni < 8; ni++)
                    mma_fp16(acc[mi][ni], ar, bw[ni]);
            }
        }
    }

    // epilogue
    int g = lane >> 2, tg = lane & 3;
    #pragma unroll
    for (int mi = 0; mi < 4; mi++) {
        #pragma unroll
        for (int ni = 0; ni < 8; ni++) {
            int col = bn + warpN + ni * 8 + tg * 2;
            #pragma unroll
            for (int half = 0; half < 2; half++) {
                int row = bm + warpM + mi * 16 + g + half * 8;
                float vx = acc[mi][ni][half * 2 + 0];
                float vy = acc[mi][ni][half * 2 + 1];
                if (BIAS) {
                    float2 bb = *(const float2*)(bias + col);
                    vx += bb.x; vy += bb.y;
                }
                size_t off = (size_t)row * N + col;
                if (RESID) {
                    float2 rr = *(const float2*)(Rm + off);
                    vx += rr.x; vy += rr.y;
                }
                if (RELU) { vx = fmaxf(vx, 0.0f); vy = fmaxf(vy, 0.0f); }
                if (HALFOUT) {
                    u32 hv = pack_h2(vx, vy);
                    *(u32*)(Ch + off) = hv;
                } else {
                    float2 o; o.x = vx; o.y = vy;
                    *(float2*)(Cf + off) = o;
                }
            }
        }
    }
}

// ---------------- tensor-core flash attention ----------------
#define ATP 72
__global__ __launch_bounds__(128) void attn_mma_kernel(const fp16* __restrict__ qkv,
                                                       fp16* __restrict__ oh) {
    __shared__ fp16 sQ[64 * ATP];
    __shared__ fp16 sKt[64 * ATP];   // transposed: sKt[d][kc]
    __shared__ fp16 sV[64 * ATP];    // sV[kc][d]

    int qt = blockIdx.x, h = blockIdx.y, b = blockIdx.z;
    int tid = threadIdx.x, lane = tid & 31, w = tid >> 5;
    int g = lane >> 2, tg = lane & 3;
    int t0 = qt * 64;
    size_t base = (size_t)b * T_ * 3072;

    const u32 sQa = smem_u32(sQ);
    const u32 sKa = smem_u32(sKt);
    const u32 sVa = smem_u32(sV);

    #pragma unroll
    for (int i = 0; i < 4; i++) {
        int idx = i * 128 + tid;
        int r = idx >> 3, c8 = (idx & 7) * 8;
        uint4 v = *(const uint4*)(qkv + base + (size_t)(t0 + r) * 3072 + h * 64 + c8);
        *(uint4*)(sQ + r * ATP + c8) = v;
    }

    float o[8][4];
    #pragma unroll
    for (int j = 0; j < 8; j++)
        #pragma unroll
        for (int c = 0; c < 4; c++) o[j][c] = 0.0f;
    float mrow[2] = {-1e30f, -1e30f};
    float lrow[2] = {0.0f, 0.0f};

    int kv_r = tid >> 1, kv_dh = (tid & 1) * 32;

    for (int ktile = 0; ktile <= qt; ++ktile) {
        __syncthreads();
        int k0 = ktile * 64;
        {
            const fp16* kp = qkv + base + (size_t)(k0 + kv_r) * 3072 + 1024 + h * 64 + kv_dh;
            #pragma unroll
            for (int c = 0; c < 4; c++) {
                uint4 v = *(const uint4*)(kp + c * 8);
                fp16 hs[8];
                *(uint4*)hs = v;
                #pragma unroll
                for (int e = 0; e < 8; e++)
                    sKt[(kv_dh + c * 8 + e) * ATP + kv_r] = hs[e];
            }
        }
        #pragma unroll
        for (int i = 0; i < 4; i++) {
            int idx = i * 128 + tid;
            int r = idx >> 3, c8 = (idx & 7) * 8;
            uint4 v = *(const uint4*)(qkv + base + (size_t)(k0 + r) * 3072 + 2048 + h * 64 + c8);
            *(uint4*)(sV + r * ATP + c8) = v;
        }
        __syncthreads();

        float cs[8][4];
        #pragma unroll
        for (int j = 0; j < 8; j++)
            #pragma unroll
            for (int c = 0; c < 4; c++) cs[j][c] = 0.0f;

        #pragma unroll
        for (int ks = 0; ks < 4; ks++) {
            u32 ar[4];
            u32 aa = sQa + (w * 16 + (lane & 7) + ((lane >> 3) & 1) * 8) * 144
                   + (lane >> 4) * 16 + ks * 32;
            ldsm4(aa, ar[0], ar[1], ar[2], ar[3]);
            #pragma unroll
            for (int j = 0; j < 8; j++) {
                u32 bw[2];
                ldsm2t(sKa + (ks * 16 + (lane & 15)) * 144 + j * 16, bw[0], bw[1]);
                mma_fp16(cs[j], ar, bw);
            }
        }

        #pragma unroll
        for (int j = 0; j < 8; j++)
            #pragma unroll
            for (int c = 0; c < 4; c++) cs[j][c] *= SCALE;
        if (ktile == qt) {
            int r0 = w * 16 + g, r1 = r0 + 8;
            #pragma unroll
            for (int j = 0; j < 8; j++) {
                int c0 = 8 * j + 2 * tg;
                if (c0 > r0) cs[j][0] = -1e30f;
                if (c0 + 1 > r0) cs[j][1] = -1e30f;
                if (c0 > r1) cs[j][2] = -1e30f;
                if (c0 + 1 > r1) cs[j][3] = -1e30f;
            }
        }

        float al[2];
        #pragma unroll
        for (int hr = 0; hr < 2; hr++) {
            float mx = -1e30f;
            #pragma unroll
            for (int j = 0; j < 8; j++)
                mx = fmaxf(mx, fmaxf(cs[j][hr * 2], cs[j][hr * 2 + 1]));
            mx = fmaxf(mx, __shfl_xor_sync(0xffffffffu, mx, 1));
            mx = fmaxf(mx, __shfl_xor_sync(0xffffffffu, mx, 2));
            float mn = fmaxf(mrow[hr], mx);
            al[hr] = __expf(mrow[hr] - mn);
            float rs = 0.0f;
            #pragma unroll
            for (int j = 0; j < 8; j++) {
                float p0 = __expf(cs[j][hr * 2] - mn);
                float p1 = __expf(cs[j][hr * 2 + 1] - mn);
                cs[j][hr * 2] = p0;
                cs[j][hr * 2 + 1] = p1;
                rs += p0 + p1;
            }
            rs += __shfl_xor_sync(0xffffffffu, rs, 1);
            rs += __shfl_xor_sync(0xffffffffu, rs, 2);
            lrow[hr] = lrow[hr] * al[hr] + rs;
            mrow[hr] = mn;
        }
        #pragma unroll
        for (int j = 0; j < 8; j++) {
            o[j][0] *= al[0]; o[j][1] *= al[0];
            o[j][2] *= al[1]; o[j][3] *= al[1];
        }

        u32 aP[4][4];
        #pragma unroll
        for (int st = 0; st < 4; st++) {
            aP[st][0] = pack_h2(cs[2 * st][0], cs[2 * st][1]);
            aP[st][1] = pack_h2(cs[2 * st][2], cs[2 * st][3]);
            aP[st][2] = pack_h2(cs[2 * st + 1][0], cs[2 * st + 1][1]);
            aP[st][3] = pack_h2(cs[2 * st + 1][2], cs[2 * st + 1][3]);
        }

        #pragma unroll
        for (int st = 0; st < 4; st++) {
            #pragma unroll
            for (int j2 = 0; j2 < 8; j2++) {
                u32 bw[2];
                ldsm2t(sVa + (st * 16 + (lane & 15)) * 144 + j2 * 16, bw[0], bw[1]);
                mma_fp16(o[j2], aP[st], bw);
            }
        }
    }

    float inv0 = 1.0f / lrow[0], inv1 = 1.0f / lrow[1];
    int r0 = t0 + w * 16 + g;
    size_t ob = ((size_t)b * T_ + r0) * E_ + h * 64;
    #pragma unroll
    for (int j = 0; j < 8; j++) {
        int col = 8 * j + 2 * tg;
        *(u32*)(oh + ob + col) = pack_h2(o[j][0] * inv0, o[j][1] * inv0);
        *(u32*)(oh + ob + 8 * E_ + col) = pack_h2(o[j][2] * inv1, o[j][3] * inv1);
    }
}

// ---------------- launch ----------------
extern "C" void kernel_launch(void* const* d_in, const int* in_sizes, int n_in,
                              void* d_out, int out_size) {
    const float* x    = (const float*)d_in[0];
    const float* Wq   = (const float*)d_in[1];
    const float* Wk   = (const float*)d_in[2];
    const float* Wv   = (const float*)d_in[3];
    const float* Wo   = (const float*)d_in[4];
    const float* bo   = (const float*)d_in[5];
    const float* W1   = (const float*)d_in[6];
    const float* b1   = (const float*)d_in[7];
    const float* W2   = (const float*)d_in[8];
    const float* b2   = (const float*)d_in[9];
    const float* ln1w = (const float*)d_in[10];
    const float* ln1b = (const float*)d_in[11];
    const float* ln2w = (const float*)d_in[12];
    const float* ln2b = (const float*)d_in[13];
    float* out = (float*)d_out;

    fp16 *h, *w3, *wo, *w1, *w2, *qkv, *attn, *u;
    float *x2;
    cudaGetSymbolAddress((void**)&h, g_h);
    cudaGetSymbolAddress((void**)&w3, g_w3);
    cudaGetSymbolAddress((void**)&wo, g_wo);
    cudaGetSymbolAddress((void**)&w1, g_w1);
    cudaGetSymbolAddress((void**)&w2, g_w2);
    cudaGetSymbolAddress((void**)&qkv, g_qkv);
    cudaGetSymbolAddress((void**)&attn, g_attn);
    cudaGetSymbolAddress((void**)&x2, g_x2);
    cudaGetSymbolAddress((void**)&u, g_u);

    cudaFuncSetAttribute(gemm_mma_kernel<false, false, false, true>,
                         cudaFuncAttributeMaxDynamicSharedMemorySize, SM_TOTAL);
    cudaFuncSetAttribute(gemm_mma_kernel<true, true, false, false>,
                         cudaFuncAttributeMaxDynamicSharedMemorySize, SM_TOTAL);
    cudaFuncSetAttribute(gemm_mma_kernel<true, false, true, true>,
                         cudaFuncAttributeMaxDynamicSharedMemorySize, SM_TOTAL);

    // weight prep
    pack_w3_kernel<<<(3 * E_ * E_) / 256, 256>>>(Wq, Wk, Wv, w3);
    quant_w_kernel<<<(E_ * E_) / 256, 256>>>(Wo, wo, E_ * E_);
    quant_w_kernel<<<(E_ * P_) / 256, 256>>>(W1, w1, E_ * P_);
    quant_w_kernel<<<(P_ * E_) / 256, 256>>>(W2, w2, P_ * E_);

    // LN1
    ln_kernel<<<M_, 256>>>(x, ln1w, ln1b, h);

    // QKV -> fp16
    gemm_mma_kernel<false, false, false, true><<<dim3(3072 / 128, M_ / 128), 128, SM_TOTAL>>>(
        h, w3, nullptr, nullptr, nullptr, qkv, 3072, E_);

    // attention (tensor cores)
    attn_mma_kernel<<<dim3(T_ / 64, H_, B_), 128>>>(qkv, attn);

    // out-proj + bias + residual(x) -> fp32 x2
    gemm_mma_kernel<true, true, false, false><<<dim3(E_ / 128, M_ / 128), 128, SM_TOTAL>>>(
        attn, wo, bo, x, x2, nullptr, E_, E_);

    // LN2
    ln_kernel<<<M_, 256>>>(x2, ln2w, ln2b, h);

    // FFN1: relu -> fp16 u
    gemm_mma_kernel<true, false, true, true><<<dim3(P_ / 128, M_ / 128), 128, SM_TOTAL>>>(
        h, w1, b1, nullptr, nullptr, u, P_, E_);

    // FFN2 -> out fp32
    gemm_mma_kernel<true, true, false, false><<<dim3(E_ / 128, M_ / 128), 128, SM_TOTAL>>>(
        u, w2, b2, x2, out, nullptr, E_, P_);
}

// round 10
// speedup vs baseline: 8.9487x; 1.1223x over previous
#include <cuda_runtime.h>
#include <cuda_fp16.h>
#include <cstdint>

#define B_  64
#define T_  320
#define E_  1024
#define H_  16
#define P_  4096
#define M_  (B_ * T_)          // 20480 tokens
#define EPS 1e-5f
#define SCALE 0.03125f          // E^-0.5

typedef unsigned u32;
typedef __half fp16;

// ---------------- scratch (device globals) ----------------
__device__ fp16 g_h[(size_t)M_ * E_];
__device__ fp16 g_w3[(size_t)E_ * 3 * E_];      // [K=1024][N=3072]
__device__ fp16 g_wo[(size_t)E_ * E_];          // [K][N]
__device__ fp16 g_w1[(size_t)E_ * P_];          // [K=1024][N=4096]
__device__ fp16 g_w2[(size_t)P_ * E_];          // [K=4096][N=1024]
__device__ fp16 g_qkv[(size_t)M_ * 3 * E_];     // fp16 q|k|v
__device__ fp16 g_attn[(size_t)M_ * E_];
__device__ float g_x2[(size_t)M_ * E_];
__device__ fp16 g_u[(size_t)M_ * P_];

// ---------------- helpers ----------------
__device__ __forceinline__ u32 smem_u32(const void* p) {
    return (u32)__cvta_generic_to_shared(p);
}
__device__ __forceinline__ u32 pack_h2(float a, float b) {
    union { __half2 h; u32 u; } c;
    c.h = __floats2half2_rn(a, b);
    return c.u;
}
__device__ __forceinline__ void cp16(u32 dst, const void* src) {
    asm volatile("cp.async.cg.shared.global [%0], [%1], 16;" :: "r"(dst), "l"(src));
}
__device__ __forceinline__ void cp_commit() { asm volatile("cp.async.commit_group;"); }
__device__ __forceinline__ void cp_wait0() { asm volatile("cp.async.wait_group 0;"); }
__device__ __forceinline__ void cp_wait1() { asm volatile("cp.async.wait_group 1;"); }

__device__ __forceinline__ void ldsm4(u32 addr, u32& r0, u32& r1, u32& r2, u32& r3) {
    asm volatile("ldmatrix.sync.aligned.m8n8.x4.shared.b16 {%0,%1,%2,%3}, [%4];"
                 : "=r"(r0), "=r"(r1), "=r"(r2), "=r"(r3) : "r"(addr));
}
__device__ __forceinline__ void ldsm4t(u32 addr, u32& r0, u32& r1, u32& r2, u32& r3) {
    asm volatile("ldmatrix.sync.aligned.m8n8.x4.trans.shared.b16 {%0,%1,%2,%3}, [%4];"
                 : "=r"(r0), "=r"(r1), "=r"(r2), "=r"(r3) : "r"(addr));
}
__device__ __forceinline__ void ldsm2(u32 addr, u32& r0, u32& r1) {
    asm volatile("ldmatrix.sync.aligned.m8n8.x2.shared.b16 {%0,%1}, [%2];"
                 : "=r"(r0), "=r"(r1) : "r"(addr));
}
__device__ __forceinline__ void ldsm2t(u32 addr, u32& r0, u32& r1) {
    asm volatile("ldmatrix.sync.aligned.m8n8.x2.trans.shared.b16 {%0,%1}, [%2];"
                 : "=r"(r0), "=r"(r1) : "r"(addr));
}
__device__ __forceinline__ void mma_fp16(float* c, const u32* a, const u32* b) {
    asm volatile("mma.sync.aligned.m16n8k16.row.col.f32.f16.f16.f32 "
                 "{%0,%1,%2,%3}, {%4,%5,%6,%7}, {%8,%9}, {%0,%1,%2,%3};"
                 : "+f"(c[0]), "+f"(c[1]), "+f"(c[2]), "+f"(c[3])
                 : "r"(a[0]), "r"(a[1]), "r"(a[2]), "r"(a[3]), "r"(b[0]), "r"(b[1]));
}
__device__ __forceinline__ void h2store4(float4 v, fp16* dst, size_t idx) {
    uint2 u;
    u.x = pack_h2(v.x, v.y);
    u.y = pack_h2(v.z, v.w);
    *(uint2*)(dst + idx) = u;
}

// ---------------- weight prep ----------------
__global__ void pack_w3_kernel(const float* __restrict__ Wq, const float* __restrict__ Wk,
                               const float* __restrict__ Wv, fp16* __restrict__ w) {
    int idx = blockIdx.x * 256 + threadIdx.x;
    int k = idx / 3072, n = idx % 3072;
    int which = n >> 10, rem = n & 1023, hh = rem >> 6, d = rem & 63;
    const float* W = (which == 0) ? Wq : (which == 1) ? Wk : Wv;
    w[idx] = __float2half_rn(W[(size_t)hh * E_ * 64 + (size_t)k * 64 + d]);
}

__global__ void quant_w_kernel(const float* __restrict__ src, fp16* __restrict__ dst, int n) {
    int idx = blockIdx.x * 256 + threadIdx.x;
    if (idx < n) dst[idx] = __float2half_rn(src[idx]);
}

// ---------------- layernorm (emits fp16) ----------------
__device__ __forceinline__ float blockSum256(float v, float* sh) {
    __syncthreads();
    #pragma unroll
    for (int o = 16; o > 0; o >>= 1) v += __shfl_xor_sync(0xffffffffu, v, o);
    if ((threadIdx.x & 31) == 0) sh[threadIdx.x >> 5] = v;
    __syncthreads();
    if (threadIdx.x < 32) {
        float t = (threadIdx.x < 8) ? sh[threadIdx.x] : 0.0f;
        #pragma unroll
        for (int o = 4; o > 0; o >>= 1) t += __shfl_xor_sync(0xffffffffu, t, o);
        if (threadIdx.x == 0) sh[0] = t;
    }
    __syncthreads();
    return sh[0];
}

__global__ void ln_kernel(const float* __restrict__ x, const float* __restrict__ w,
                          const float* __restrict__ bb, fp16* __restrict__ out) {
    __shared__ float sh[8];
    size_t row = blockIdx.x;
    int tid = threadIdx.x;
    const float4 v = ((const float4*)(x + row * E_))[tid];
    float s = v.x + v.y + v.z + v.w;
    s = blockSum256(s, sh);
    float mu = s * (1.0f / E_);
    float dx = v.x - mu, dy = v.y - mu, dz = v.z - mu, dw = v.w - mu;
    float ss = dx * dx + dy * dy + dz * dz + dw * dw;
    ss = blockSum256(ss, sh);
    float inv = rsqrtf(ss * (1.0f / E_) + EPS);
    float4 w4 = ((const float4*)w)[tid];
    float4 b4 = ((const float4*)bb)[tid];
    float4 r;
    r.x = dx * inv * w4.x + b4.x;
    r.y = dy * inv * w4.y + b4.y;
    r.z = dz * inv * w4.z + b4.z;
    r.w = dw * inv * w4.w + b4.w;
    h2store4(r, out, row * E_ + tid * 4);
}

// ---------------- single-pass fp16 tensor-core GEMM, 3-stage pipeline ----------------
// CTA 128x128, 4 warps (2x2), warp tile 64x64. K-stage 32.
// smem per stage: A[128][40] (80B pitch), B[32][136] (272B pitch)
#define A_BYTES 10240
#define B_BYTES 8704
#define STAGE_BYTES (A_BYTES + B_BYTES)
#define SM_TOTAL (3 * STAGE_BYTES)      // 56832

template <bool BIAS, bool RESID, bool RELU, bool HALFOUT>
__global__ __launch_bounds__(128, 2) void gemm_mma_kernel(
    const fp16* __restrict__ Aw, const fp16* __restrict__ Bw,
    const float* __restrict__ bias, const float* __restrict__ Rm,
    float* __restrict__ Cf, fp16* __restrict__ Ch,
    int N, int K) {
    extern __shared__ char sm[];
    const u32 smb = smem_u32(sm);

    int tid = threadIdx.x;
    int lane = tid & 31, wid = tid >> 5;
    int warpM = (wid >> 1) * 64, warpN = (wid & 1) * 64;
    int bm = blockIdx.y * 128, bn = blockIdx.x * 128;

    int a_cr = tid >> 2, a_cc = tid & 3;
    int b_cr = tid >> 4, b_cc = tid & 15;
    u32 a_dst0 = a_cr * 80 + a_cc * 16;
    u32 b_dst0 = b_cr * 272 + b_cc * 16;

    u32 a_off = (warpM + (lane & 15)) * 80 + (lane >> 4) * 16;
    u32 b_off = (lane & 15) * 272 + warpN * 2 + (lane >> 4) * 16;

    auto load_stage = [&](u32 sb, int k0) {
        #pragma unroll
        for (int c = 0; c < 4; c++) {
            cp16(sb + a_dst0 + c * 32 * 80,
                 Aw + (size_t)(bm + a_cr + c * 32) * K + k0 + a_cc * 8);
            cp16(sb + A_BYTES + b_dst0 + c * 8 * 272,
                 Bw + (size_t)(k0 + b_cr + c * 8) * N + bn + b_cc * 8);
        }
        cp_commit();
    };

    float acc[4][8][4];
    #pragma unroll
    for (int i = 0; i < 4; i++)
        #pragma unroll
        for (int j = 0; j < 8; j++)
            #pragma unroll
            for (int c = 0; c < 4; c++) acc[i][j][c] = 0.0f;

    const int nk = K >> 5;

    // prologue: stages 0 and 1 in flight
    load_stage(smb, 0);
    load_stage(smb + STAGE_BYTES, 32);

    for (int kt = 0; kt < nk; kt++) {
        if (kt + 1 < nk) cp_wait1(); else cp_wait0();
        __syncthreads();
        u32 cur = smb + (u32)(kt % 3) * STAGE_BYTES;

        if (kt + 2 < nk)
            load_stage(smb + (u32)((kt + 2) % 3) * STAGE_BYTES, (kt + 2) * 32);

        #pragma unroll
        for (int ks = 0; ks < 2; ks++) {
            u32 bw[8][2];
            #pragma unroll
            for (int nj = 0; nj < 4; nj++) {
                u32 ba = cur + A_BYTES + b_off + nj * 32 + ks * 4352;
                ldsm4t(ba, bw[2 * nj][0], bw[2 * nj][1], bw[2 * nj + 1][0], bw[2 * nj + 1][1]);
            }
            #pragma unroll
            for (int mi = 0; mi < 4; mi++) {
                u32 ar[4];
                u32 aa = cur + a_off + mi * 1280 + ks * 32;
                ldsm4(aa, ar[0], ar[1], ar[2], ar[3]);
                #pragma unroll
                for (int ni = 0; ni < 8; ni++)
                    mma_fp16(acc[mi][ni], ar, bw[ni]);
            }
        }
    }

    // epilogue
    int g = lane >> 2, tg = lane & 3;
    #pragma unroll
    for (int mi = 0; mi < 4; mi++) {
        #pragma unroll
        for (int ni = 0; ni < 8; ni++) {
            int col = bn + warpN + ni * 8 + tg * 2;
            #pragma unroll
            for (int half = 0; half < 2; half++) {
                int row = bm + warpM + mi * 16 + g + half * 8;
                float vx = acc[mi][ni][half * 2 + 0];
                float vy = acc[mi][ni][half * 2 + 1];
                if (BIAS) {
                    float2 bb = *(const float2*)(bias + col);
                    vx += bb.x; vy += bb.y;
                }
                size_t off = (size_t)row * N + col;
                if (RESID) {
                    float2 rr = *(const float2*)(Rm + off);
                    vx += rr.x; vy += rr.y;
                }
                if (RELU) { vx = fmaxf(vx, 0.0f); vy = fmaxf(vy, 0.0f); }
                if (HALFOUT) {
                    u32 hv = pack_h2(vx, vy);
                    *(u32*)(Ch + off) = hv;
                } else {
                    float2 o; o.x = vx; o.y = vy;
                    *(float2*)(Cf + off) = o;
                }
            }
        }
    }
}

// ---------------- tensor-core flash attention (cp.async KV pipeline) ----------------
// K stored row-major [kc][d] and consumed with NON-transposed ldmatrix:
// for S = Q K^T with mma.row.col, K[kc][d] IS B in col-major layout.
#define ATP 72
__global__ __launch_bounds__(128) void attn_mma_kernel(const fp16* __restrict__ qkv,
                                                       fp16* __restrict__ oh) {
    __shared__ fp16 sQ[64 * ATP];
    __shared__ fp16 sK[2][64 * ATP];
    __shared__ fp16 sV[2][64 * ATP];

    int qt = blockIdx.x, h = blockIdx.y, b = blockIdx.z;
    int tid = threadIdx.x, lane = tid & 31, w = tid >> 5;
    int g = lane >> 2, tg = lane & 3;
    int t0 = qt * 64;
    size_t base = (size_t)b * T_ * 3072;

    const u32 sQa = smem_u32(sQ);
    const u32 sKa0 = smem_u32(sK);
    const u32 sVa0 = smem_u32(sV);

    // per-thread copy coords: 4 chunks of 16B per tile
    int cp_r[4], cp_c[4];
    #pragma unroll
    for (int i = 0; i < 4; i++) {
        int idx = i * 128 + tid;
        cp_r[i] = idx >> 3;
        cp_c[i] = (idx & 7) * 8;
    }

    // group 0: Q + KV tile 0
    #pragma unroll
    for (int i = 0; i < 4; i++)
        cp16(sQa + cp_r[i] * 144 + cp_c[i] * 2,
             qkv + base + (size_t)(t0 + cp_r[i]) * 3072 + h * 64 + cp_c[i]);
    #pragma unroll
    for (int i = 0; i < 4; i++) {
        cp16(sKa0 + cp_r[i] * 144 + cp_c[i] * 2,
             qkv + base + (size_t)cp_r[i] * 3072 + 1024 + h * 64 + cp_c[i]);
        cp16(sVa0 + cp_r[i] * 144 + cp_c[i] * 2,
             qkv + base + (size_t)cp_r[i] * 3072 + 2048 + h * 64 + cp_c[i]);
    }
    cp_commit();

    float o[8][4];
    #pragma unroll
    for (int j = 0; j < 8; j++)
        #pragma unroll
        for (int c = 0; c < 4; c++) o[j][c] = 0.0f;
    float mrow[2] = {-1e30f, -1e30f};
    float lrow[2] = {0.0f, 0.0f};

    int buf = 0;
    for (int ktile = 0; ktile <= qt; ++ktile) {
        cp_wait0();
        __syncthreads();
        int nbuf = buf ^ 1;
        if (ktile < qt) {
            int k1 = (ktile + 1) * 64;
            u32 kd = sKa0 + (u32)nbuf * (64 * ATP * 2);
            u32 vd = sVa0 + (u32)nbuf * (64 * ATP * 2);
            #pragma unroll
            for (int i = 0; i < 4; i++) {
                cp16(kd + cp_r[i] * 144 + cp_c[i] * 2,
                     qkv + base + (size_t)(k1 + cp_r[i]) * 3072 + 1024 + h * 64 + cp_c[i]);
                cp16(vd + cp_r[i] * 144 + cp_c[i] * 2,
                     qkv + base + (size_t)(k1 + cp_r[i]) * 3072 + 2048 + h * 64 + cp_c[i]);
            }
            cp_commit();
        }

        u32 sKb = sKa0 + (u32)buf * (64 * ATP * 2);
        u32 sVb = sVa0 + (u32)buf * (64 * ATP * 2);

        // S = Q(16x64) @ K^T
        float cs[8][4];
        #pragma unroll
        for (int j = 0; j < 8; j++)
            #pragma unroll
            for (int c = 0; c < 4; c++) cs[j][c] = 0.0f;

        #pragma unroll
        for (int ks = 0; ks < 4; ks++) {
            u32 ar[4];
            u32 aa = sQa + (w * 16 + (lane & 7) + ((lane >> 3) & 1) * 8) * 144
                   + (lane >> 4) * 16 + ks * 32;
            ldsm4(aa, ar[0], ar[1], ar[2], ar[3]);
            #pragma unroll
            for (int j = 0; j < 8; j++) {
                u32 bw[2];
                // non-trans: lanes 0-15 address rows kc = 8j..8j+7, d-halves ks*16 + (0|8)
                ldsm2(sKb + (8 * j + (lane & 7)) * 144 + ks * 32 + ((lane >> 3) & 1) * 16,
                      bw[0], bw[1]);
                mma_fp16(cs[j], ar, bw);
            }
        }

        #pragma unroll
        for (int j = 0; j < 8; j++)
            #pragma unroll
            for (int c = 0; c < 4; c++) cs[j][c] *= SCALE;
        if (ktile == qt) {
            int r0 = w * 16 + g, r1 = r0 + 8;
            #pragma unroll
            for (int j = 0; j < 8; j++) {
                int c0 = 8 * j + 2 * tg;
                if (c0 > r0) cs[j][0] = -1e30f;
                if (c0 + 1 > r0) cs[j][1] = -1e30f;
                if (c0 > r1) cs[j][2] = -1e30f;
                if (c0 + 1 > r1) cs[j][3] = -1e30f;
            }
        }

        float al[2];
        #pragma unroll
        for (int hr = 0; hr < 2; hr++) {
            float mx = -1e30f;
            #pragma unroll
            for (int j = 0; j < 8; j++)
                mx = fmaxf(mx, fmaxf(cs[j][hr * 2], cs[j][hr * 2 + 1]));
            mx = fmaxf(mx, __shfl_xor_sync(0xffffffffu, mx, 1));
            mx = fmaxf(mx, __shfl_xor_sync(0xffffffffu, mx, 2));
            float mn = fmaxf(mrow[hr], mx);
            al[hr] = __expf(mrow[hr] - mn);
            float rs = 0.0f;
            #pragma unroll
            for (int j = 0; j < 8; j++) {
                float p0 = __expf(cs[j][hr * 2] - mn);
                float p1 = __expf(cs[j][hr * 2 + 1] - mn);
                cs[j][hr * 2] = p0;
                cs[j][hr * 2 + 1] = p1;
                rs += p0 + p1;
            }
            rs += __shfl_xor_sync(0xffffffffu, rs, 1);
            rs += __shfl_xor_sync(0xffffffffu, rs, 2);
            lrow[hr] = lrow[hr] * al[hr] + rs;
            mrow[hr] = mn;
        }
        #pragma unroll
        for (int j = 0; j < 8; j++) {
            o[j][0] *= al[0]; o[j][1] *= al[0];
            o[j][2] *= al[1]; o[j][3] *= al[1];
        }

        // P fragments (C-frag -> A-frag identity)
        u32 aP[4][4];
        #pragma unroll
        for (int st = 0; st < 4; st++) {
            aP[st][0] = pack_h2(cs[2 * st][0], cs[2 * st][1]);
            aP[st][1] = pack_h2(cs[2 * st][2], cs[2 * st][3]);
            aP[st][2] = pack_h2(cs[2 * st + 1][0], cs[2 * st + 1][1]);
            aP[st][3] = pack_h2(cs[2 * st + 1][2], cs[2 * st + 1][3]);
        }

        // O += P(16x64) @ V(64x64)  (V [kc][d] needs trans ldmatrix)
        #pragma unroll
        for (int st = 0; st < 4; st++) {
            #pragma unroll
            for (int j2 = 0; j2 < 8; j2++) {
                u32 bw[2];
                ldsm2t(sVb + (st * 16 + (lane & 15)) * 144 + j2 * 16, bw[0], bw[1]);
                mma_fp16(o[j2], aP[st], bw);
            }
        }
        buf = nbuf;
    }

    float inv0 = 1.0f / lrow[0], inv1 = 1.0f / lrow[1];
    int r0 = t0 + w * 16 + g;
    size_t ob = ((size_t)b * T_ + r0) * E_ + h * 64;
    #pragma unroll
    for (int j = 0; j < 8; j++) {
        int col = 8 * j + 2 * tg;
        *(u32*)(oh + ob + col) = pack_h2(o[j][0] * inv0, o[j][1] * inv0);
        *(u32*)(oh + ob + 8 * E_ + col) = pack_h2(o[j][2] * inv1, o[j][3] * inv1);
    }
}

// ---------------- launch ----------------
extern "C" void kernel_launch(void* const* d_in, const int* in_sizes, int n_in,
                              void* d_out, int out_size) {
    const float* x    = (const float*)d_in[0];
    const float* Wq   = (const float*)d_in[1];
    const float* Wk   = (const float*)d_in[2];
    const float* Wv   = (const float*)d_in[3];
    const float* Wo   = (const float*)d_in[4];
    const float* bo   = (const float*)d_in[5];
    const float* W1   = (const float*)d_in[6];
    const float* b1   = (const float*)d_in[7];
    const float* W2   = (const float*)d_in[8];
    const float* b2   = (const float*)d_in[9];
    const float* ln1w = (const float*)d_in[10];
    const float* ln1b = (const float*)d_in[11];
    const float* ln2w = (const float*)d_in[12];
    const float* ln2b = (const float*)d_in[13];
    float* out = (float*)d_out;

    fp16 *h, *w3, *wo, *w1, *w2, *qkv, *attn, *u;
    float *x2;
    cudaGetSymbolAddress((void**)&h, g_h);
    cudaGetSymbolAddress((void**)&w3, g_w3);
    cudaGetSymbolAddress((void**)&wo, g_wo);
    cudaGetSymbolAddress((void**)&w1, g_w1);
    cudaGetSymbolAddress((void**)&w2, g_w2);
    cudaGetSymbolAddress((void**)&qkv, g_qkv);
    cudaGetSymbolAddress((void**)&attn, g_attn);
    cudaGetSymbolAddress((void**)&x2, g_x2);
    cudaGetSymbolAddress((void**)&u, g_u);

    cudaFuncSetAttribute(gemm_mma_kernel<false, false, false, true>,
                         cudaFuncAttributeMaxDynamicSharedMemorySize, SM_TOTAL);
    cudaFuncSetAttribute(gemm_mma_kernel<true, true, false, false>,
                         cudaFuncAttributeMaxDynamicSharedMemorySize, SM_TOTAL);
    cudaFuncSetAttribute(gemm_mma_kernel<true, false, true, true>,
                         cudaFuncAttributeMaxDynamicSharedMemorySize, SM_TOTAL);

    // weight prep
    pack_w3_kernel<<<(3 * E_ * E_) / 256, 256>>>(Wq, Wk, Wv, w3);
    quant_w_kernel<<<(E_ * E_) / 256, 256>>>(Wo, wo, E_ * E_);
    quant_w_kernel<<<(E_ * P_) / 256, 256>>>(W1, w1, E_ * P_);
    quant_w_kernel<<<(P_ * E_) / 256, 256>>>(W2, w2, P_ * E_);

    // LN1
    ln_kernel<<<M_, 256>>>(x, ln1w, ln1b, h);

    // QKV -> fp16
    gemm_mma_kernel<false, false, false, true><<<dim3(3072 / 128, M_ / 128), 128, SM_TOTAL>>>(
        h, w3, nullptr, nullptr, nullptr, qkv, 3072, E_);

    // attention (tensor cores)
    attn_mma_kernel<<<dim3(T_ / 64, H_, B_), 128>>>(qkv, attn);

    // out-proj + bias + residual(x) -> fp32 x2
    gemm_mma_kernel<true, true, false, false><<<dim3(E_ / 128, M_ / 128), 128, SM_TOTAL>>>(
        attn, wo, bo, x, x2, nullptr, E_, E_);

    // LN2
    ln_kernel<<<M_, 256>>>(x2, ln2w, ln2b, h);

    // FFN1: relu -> fp16 u
    gemm_mma_kernel<true, false, true, true><<<dim3(P_ / 128, M_ / 128), 128, SM_TOTAL>>>(
        h, w1, b1, nullptr, nullptr, u, P_, E_);

    // FFN2 -> out fp32
    gemm_mma_kernel<true, true, false, false><<<dim3(E_ / 128, M_ / 128), 128, SM_TOTAL>>>(
        u, w2, b2, x2, out, nullptr, E_, P_);
}